// round 8
// baseline (speedup 1.0000x reference)
#include <cuda_runtime.h>
#include <cuda_bf16.h>
#include <math.h>
#include <stdint.h>

// Problem dims (fixed by dataset)
#define Bc 8
#define Sc 4096
#define Tc 512
#define Dc 1024
#define NEG_NUM -10000.0f

// ---------------------------------------------------------------------------
// Scratch (device globals; no allocations allowed)
// ---------------------------------------------------------------------------
__device__ __nv_bfloat16 g_Chi [(size_t)Bc * Sc * Dc];
__device__ __nv_bfloat16 g_Clo [(size_t)Bc * Sc * Dc];
__device__ __nv_bfloat16 g_Qhi [(size_t)Bc * Tc * Dc];
__device__ __nv_bfloat16 g_Qlo [(size_t)Bc * Tc * Dc];
__device__ __nv_bfloat16 g_Phi [(size_t)Bc * Tc * Sc];
__device__ __nv_bfloat16 g_Plo [(size_t)Bc * Tc * Sc];
__device__ float         g_p_scratch[(size_t)Bc * Tc * Sc];

// ---------------------------------------------------------------------------
// PTX helpers (baseline PTX only: cp.async, ldmatrix, mma.sync)
// ---------------------------------------------------------------------------
__device__ __forceinline__ uint32_t smem_u32(const void* p) {
    uint32_t a;
    asm("{ .reg .u64 t; cvta.to.shared.u64 t, %1; cvt.u32.u64 %0, t; }" : "=r"(a) : "l"(p));
    return a;
}

__device__ __forceinline__ void cp_async16(uint32_t dst, const void* src) {
    asm volatile("cp.async.cg.shared.global [%0], [%1], 16;" :: "r"(dst), "l"(src));
}
#define CP_COMMIT() asm volatile("cp.async.commit_group;" ::: "memory")
#define CP_WAIT2()  asm volatile("cp.async.wait_group 2;"  ::: "memory")

__device__ __forceinline__ void ldsm_x4(uint32_t* r, uint32_t addr) {
    asm volatile("ldmatrix.sync.aligned.m8n8.x4.shared.b16 {%0,%1,%2,%3}, [%4];"
                 : "=r"(r[0]), "=r"(r[1]), "=r"(r[2]), "=r"(r[3]) : "r"(addr));
}
__device__ __forceinline__ void ldsm_x4_t(uint32_t* r, uint32_t addr) {
    asm volatile("ldmatrix.sync.aligned.m8n8.x4.trans.shared.b16 {%0,%1,%2,%3}, [%4];"
                 : "=r"(r[0]), "=r"(r[1]), "=r"(r[2]), "=r"(r[3]) : "r"(addr));
}
__device__ __forceinline__ void mma16816(float* d, const uint32_t* a, uint32_t b0, uint32_t b1) {
    asm volatile(
        "mma.sync.aligned.m16n8k16.row.col.f32.bf16.bf16.f32 "
        "{%0,%1,%2,%3}, {%4,%5,%6,%7}, {%8,%9}, {%0,%1,%2,%3};"
        : "+f"(d[0]), "+f"(d[1]), "+f"(d[2]), "+f"(d[3])
        : "r"(a[0]), "r"(a[1]), "r"(a[2]), "r"(a[3]), "r"(b0), "r"(b1));
}

// smem layout (dynamic): [0,512) mask | [1024, +3*64KB) stages
#define SM_MASK    0
#define SM_STAGE0  1024
#define TILE_BYTES_ 16384          // per-operand tile (16KB)
#define STAGE_BYTES 65536          // Ahi, Alo, Bhi, Blo
#define SMEM_TOTAL (SM_STAGE0 + 3 * STAGE_BYTES)   // 197632

// ---------------------------------------------------------------------------
// bf16x3 split GEMM via mma.sync: D[m,n] = sum_k A[m,k]*B[n,k]
// CTA tile 128x128, 8 warps (2x4), warp tile 64x32, BK=64, 3-stage cp.async.
// IS_QK=true : B tile stored [n][k] (128 rows x 128B), non-trans ldmatrix.
// IS_QK=false: B = C natural [k=s][n=d] (64 rows x 256B), TRANS ldmatrix.
// ---------------------------------------------------------------------------
template <int KTOT, bool IS_QK>
__global__ __launch_bounds__(256, 1) void gemm_hmma(
    const __nv_bfloat16* __restrict__ Ahi, const __nv_bfloat16* __restrict__ Alo,
    const __nv_bfloat16* __restrict__ Bhi, const __nv_bfloat16* __restrict__ Blo,
    const int* __restrict__ mask, float* __restrict__ Out,
    int lda, int ldb, int ldo, size_t strA, size_t strB, size_t strO)
{
    extern __shared__ __align__(1024) char smem[];
    const uint32_t sb  = smem_u32(smem);
    const int tid  = threadIdx.x;
    const int lane = tid & 31;
    const int wid  = tid >> 5;
    const int wm   = wid & 1;        // 2 warp-rows of 64
    const int wn   = wid >> 1;       // 4 warp-cols of 32
    const int b    = blockIdx.z;
    const int n0   = blockIdx.x * 128;
    const int m0   = blockIdx.y * 128;
    constexpr int NST = KTOT / 64;

    int* smask = (int*)(smem + SM_MASK);
    if (IS_QK && tid < 128) smask[tid] = mask[b * Sc + n0 + tid];

    // ---- cp.async load geometry ----
    // A: 128 rows x 128B, 8 chunks/row; 4 chunks per thread per operand.
    uint32_t swzA[4];
    size_t   ga[4];
    // B: QK same as A on n-rows; PV: 64 rows x 256B, 16 chunks/row.
    uint32_t swzB[4];
    size_t   gb[4];
#pragma unroll
    for (int j = 0; j < 4; j++) {
        int within = tid + 256 * j;
        {   // A geometry
            int row = within >> 3;
            int u   = within & 7;
            uint32_t off = (uint32_t)(row * 128 + u * 16);
            swzA[j] = off ^ ((off >> 3) & 0x70);
            ga[j]   = (size_t)(m0 + row) * lda + u * 8;
        }
        if (IS_QK) {
            int row = within >> 3;
            int u   = within & 7;
            uint32_t off = (uint32_t)(row * 128 + u * 16);
            swzB[j] = off ^ ((off >> 3) & 0x70);
            gb[j]   = (size_t)(n0 + row) * ldb + u * 8;
        } else {
            int r   = within >> 4;          // 0..63 (k rows)
            int c16 = within & 15;          // 16B chunk within 256B row
            swzB[j] = (uint32_t)(r * 256 + ((c16 * 16) ^ ((r & 7) << 4)));
            gb[j]   = (size_t)r * ldb + n0 + c16 * 8;
        }
    }
    const __nv_bfloat16* Ah = Ahi + (size_t)b * strA;
    const __nv_bfloat16* Al = Alo + (size_t)b * strA;
    const __nv_bfloat16* Bh = Bhi + (size_t)b * strB;
    const __nv_bfloat16* Bl = Blo + (size_t)b * strB;

    auto load_stage = [&](int k) {
        const uint32_t stg = sb + SM_STAGE0 + (k % 3) * STAGE_BYTES;
        const size_t kA = (size_t)k * 64;                       // A: k along row
        const size_t kB = IS_QK ? (size_t)k * 64                // B rows fixed, k along row
                                : (size_t)k * 64 * ldb;         // B: k advances rows
#pragma unroll
        for (int j = 0; j < 4; j++) {
            cp_async16(stg + 0 * TILE_BYTES_ + swzA[j], Ah + ga[j] + kA);
            cp_async16(stg + 1 * TILE_BYTES_ + swzA[j], Al + ga[j] + kA);
            cp_async16(stg + 2 * TILE_BYTES_ + swzB[j], Bh + gb[j] + kB);
            cp_async16(stg + 3 * TILE_BYTES_ + swzB[j], Bl + gb[j] + kB);
        }
    };

    // ---- ldmatrix lane addressing ----
    // A tiles (non-trans): 16x16 at (wm*64 + mt*16, kk)
    uint32_t apart[4], aswz[4];
#pragma unroll
    for (int mt = 0; mt < 4; mt++) {
        int r = wm * 64 + mt * 16 + (lane & 15);
        apart[mt] = (uint32_t)r * 128;
        aswz[mt]  = (uint32_t)((r & 7) << 4);
    }
    const uint32_t acol = (uint32_t)((lane >> 4) * 16);

    // B QK (non-trans, [n][k] 128B rows)
    uint32_t bpartQ[2], bswzQ[2];
    uint32_t bcolQ = 0;
    // B PV (trans, [k][n] 256B rows): per-lane constant offset, + kk*256
    uint32_t boffP[2];
    {
        int g  = lane >> 3;
        int lr = lane & 7;
        if (IS_QK) {
            int j = g >> 1;
#pragma unroll
            for (int p = 0; p < 2; p++) {
                int r = wn * 32 + p * 16 + j * 8 + lr;
                bpartQ[p] = (uint32_t)r * 128;
                bswzQ[p]  = (uint32_t)((r & 7) << 4);
            }
            bcolQ = (uint32_t)((g & 1) * 16);
        } else {
            int rbase = (g >> 1) * 8 + lr;          // k row within 16-row group
#pragma unroll
            for (int p = 0; p < 2; p++) {
                int ncol = wn * 32 + p * 16 + (g & 1) * 8;   // local d col
                boffP[p] = (uint32_t)(rbase * 256 + ((ncol * 2) ^ ((rbase & 7) << 4)));
            }
        }
    }

    float acc[4][4][4];
#pragma unroll
    for (int mt = 0; mt < 4; mt++)
#pragma unroll
        for (int nt = 0; nt < 4; nt++)
#pragma unroll
            for (int f = 0; f < 4; f++) acc[mt][nt][f] = 0.0f;

    // ---- pipeline ----
    load_stage(0); CP_COMMIT();
    load_stage(1); CP_COMMIT();

    for (int k = 0; k < NST; k++) {
        if (k + 2 < NST) load_stage(k + 2);
        CP_COMMIT();
        CP_WAIT2();            // stage k's group retired
        __syncthreads();

        const uint32_t stg = sb + SM_STAGE0 + (k % 3) * STAGE_BYTES;
#pragma unroll
        for (int kk = 0; kk < 64; kk += 16) {
            uint32_t ahi[4][4], alo[4][4], bhi[2][4], blo[2][4];
            const uint32_t ac = (uint32_t)(kk * 2) + acol;
#pragma unroll
            for (int mt = 0; mt < 4; mt++) {
                ldsm_x4(ahi[mt], stg + 0 * TILE_BYTES_ + apart[mt] + (ac ^ aswz[mt]));
                ldsm_x4(alo[mt], stg + 1 * TILE_BYTES_ + apart[mt] + (ac ^ aswz[mt]));
            }
            if (IS_QK) {
                const uint32_t bc = (uint32_t)(kk * 2) + bcolQ;
#pragma unroll
                for (int p = 0; p < 2; p++) {
                    ldsm_x4(bhi[p], stg + 2 * TILE_BYTES_ + bpartQ[p] + (bc ^ bswzQ[p]));
                    ldsm_x4(blo[p], stg + 3 * TILE_BYTES_ + bpartQ[p] + (bc ^ bswzQ[p]));
                }
            } else {
                const uint32_t kb = (uint32_t)(kk * 256);
#pragma unroll
                for (int p = 0; p < 2; p++) {
                    ldsm_x4_t(bhi[p], stg + 2 * TILE_BYTES_ + kb + boffP[p]);
                    ldsm_x4_t(blo[p], stg + 3 * TILE_BYTES_ + kb + boffP[p]);
                }
            }
#pragma unroll
            for (int mt = 0; mt < 4; mt++)
#pragma unroll
                for (int nt = 0; nt < 4; nt++) {
                    const int p = nt >> 1;
                    uint32_t h0, h1, l0, l1;
                    if (IS_QK) {
                        const int o = (nt & 1) * 2;
                        h0 = bhi[p][o]; h1 = bhi[p][o + 1];
                        l0 = blo[p][o]; l1 = blo[p][o + 1];
                    } else {
                        const int j = nt & 1;
                        h0 = bhi[p][j]; h1 = bhi[p][j + 2];
                        l0 = blo[p][j]; l1 = blo[p][j + 2];
                    }
                    mma16816(acc[mt][nt], ahi[mt], h0, h1);
                    mma16816(acc[mt][nt], ahi[mt], l0, l1);
                    mma16816(acc[mt][nt], alo[mt], h0, h1);
                }
        }
        __syncthreads();       // all warps done reading stage k (buffer reuse)
    }

    // ---- epilogue ----
    const int r0 = lane >> 2;
    const int c0 = (lane & 3) * 2;
    float* Ob = Out + (size_t)b * strO;
#pragma unroll
    for (int mt = 0; mt < 4; mt++) {
        const int row = m0 + wm * 64 + mt * 16 + r0;
#pragma unroll
        for (int nt = 0; nt < 4; nt++) {
            const int col = n0 + wn * 32 + nt * 8 + c0;
            float* d = acc[mt][nt];
            if (IS_QK) {
                const float scale = 0.03125f;  // 1/sqrt(1024)
                const int mcol = wn * 32 + nt * 8 + c0;
                const int mk0 = smask[mcol], mk1 = smask[mcol + 1];
                float2 v0, v1;
                v0.x = mk0 ? d[0] * scale : NEG_NUM;
                v0.y = mk1 ? d[1] * scale : NEG_NUM;
                v1.x = mk0 ? d[2] * scale : NEG_NUM;
                v1.y = mk1 ? d[3] * scale : NEG_NUM;
                *(float2*)(Ob + (size_t)row * ldo + col)       = v0;
                *(float2*)(Ob + (size_t)(row + 8) * ldo + col) = v1;
            } else {
                *(float2*)(Ob + (size_t)row * ldo + col)       = make_float2(d[0], d[1]);
                *(float2*)(Ob + (size_t)(row + 8) * ldo + col) = make_float2(d[2], d[3]);
            }
        }
    }
}

// ---------------------------------------------------------------------------
// Convert C -> (Chi, Clo): pure streaming, 4 floats/thread
// ---------------------------------------------------------------------------
__global__ __launch_bounds__(256) void convert_C_kernel(const float* __restrict__ C)
{
    size_t i = ((size_t)blockIdx.x * 256 + threadIdx.x) * 4;
    float4 v = *(const float4*)(C + i);
    __nv_bfloat162 h01 = __floats2bfloat162_rn(v.x, v.y);
    __nv_bfloat162 h23 = __floats2bfloat162_rn(v.z, v.w);
    __nv_bfloat162 l01 = __floats2bfloat162_rn(v.x - __bfloat162float(__low2bfloat16(h01)),
                                               v.y - __bfloat162float(__high2bfloat16(h01)));
    __nv_bfloat162 l23 = __floats2bfloat162_rn(v.z - __bfloat162float(__low2bfloat16(h23)),
                                               v.w - __bfloat162float(__high2bfloat16(h23)));
    *(__nv_bfloat162*)(g_Chi + i)     = h01;
    *(__nv_bfloat162*)(g_Chi + i + 2) = h23;
    *(__nv_bfloat162*)(g_Clo + i)     = l01;
    *(__nv_bfloat162*)(g_Clo + i + 2) = l23;
}

// ---------------------------------------------------------------------------
// Convert Q -> (Qhi, Qlo)
// ---------------------------------------------------------------------------
__global__ __launch_bounds__(256) void convert_Q_kernel(const float* __restrict__ Q)
{
    size_t i = ((size_t)blockIdx.x * 256 + threadIdx.x) * 4;
    float4 v = *(const float4*)(Q + i);
    __nv_bfloat162 h01 = __floats2bfloat162_rn(v.x, v.y);
    __nv_bfloat162 h23 = __floats2bfloat162_rn(v.z, v.w);
    __nv_bfloat162 l01 = __floats2bfloat162_rn(v.x - __bfloat162float(__low2bfloat16(h01)),
                                               v.y - __bfloat162float(__high2bfloat16(h01)));
    __nv_bfloat162 l23 = __floats2bfloat162_rn(v.z - __bfloat162float(__low2bfloat16(h23)),
                                               v.w - __bfloat162float(__high2bfloat16(h23)));
    *(__nv_bfloat162*)(g_Qhi + i)     = h01;
    *(__nv_bfloat162*)(g_Qhi + i + 2) = h23;
    *(__nv_bfloat162*)(g_Qlo + i)     = l01;
    *(__nv_bfloat162*)(g_Qlo + i + 2) = l23;
}

// ---------------------------------------------------------------------------
// Softmax over S=4096, in place; emits p fp32 + (Phi, Plo) bf16. __expf path.
// ---------------------------------------------------------------------------
__global__ __launch_bounds__(256) void softmax_kernel(float* __restrict__ P)
{
    const size_t row = blockIdx.x;
    float* p = P + row * Sc;
    const int tid  = threadIdx.x;
    const int warp = tid >> 5;
    const int lane = tid & 31;
    const int base = tid * 16;

    __shared__ float red_max[8];
    __shared__ float red_sum[8];

    float v[16];
#pragma unroll
    for (int i = 0; i < 4; i++) {
        float4 a = *(const float4*)(p + base + i * 4);
        v[i * 4 + 0] = a.x; v[i * 4 + 1] = a.y; v[i * 4 + 2] = a.z; v[i * 4 + 3] = a.w;
    }
    float m = -1e30f;
#pragma unroll
    for (int i = 0; i < 16; i++) m = fmaxf(m, v[i]);
#pragma unroll
    for (int off = 16; off > 0; off >>= 1)
        m = fmaxf(m, __shfl_xor_sync(0xffffffffu, m, off));
    if (lane == 0) red_max[warp] = m;
    __syncthreads();
    float bm = red_max[0];
#pragma unroll
    for (int w = 1; w < 8; w++) bm = fmaxf(bm, red_max[w]);

    float s = 0.0f;
#pragma unroll
    for (int i = 0; i < 16; i++) { v[i] = __expf(v[i] - bm); s += v[i]; }
#pragma unroll
    for (int off = 16; off > 0; off >>= 1)
        s += __shfl_xor_sync(0xffffffffu, s, off);
    if (lane == 0) red_sum[warp] = s;
    __syncthreads();
    float tot = 0.0f;
#pragma unroll
    for (int w = 0; w < 8; w++) tot += red_sum[w];
    const float inv = 1.0f / tot;

    __nv_bfloat16* ph = g_Phi + row * Sc + base;
    __nv_bfloat16* pl = g_Plo + row * Sc + base;
#pragma unroll
    for (int i = 0; i < 4; i++) {
        float4 a;
        a.x = v[i * 4 + 0] * inv; a.y = v[i * 4 + 1] * inv;
        a.z = v[i * 4 + 2] * inv; a.w = v[i * 4 + 3] * inv;
        *(float4*)(p + base + i * 4) = a;
        __nv_bfloat162 h01 = __floats2bfloat162_rn(a.x, a.y);
        __nv_bfloat162 h23 = __floats2bfloat162_rn(a.z, a.w);
        __nv_bfloat162 l01 = __floats2bfloat162_rn(a.x - __bfloat162float(__low2bfloat16(h01)),
                                                   a.y - __bfloat162float(__high2bfloat16(h01)));
        __nv_bfloat162 l23 = __floats2bfloat162_rn(a.z - __bfloat162float(__low2bfloat16(h23)),
                                                   a.w - __bfloat162float(__high2bfloat16(h23)));
        *(__nv_bfloat162*)(ph + i * 4)     = h01;
        *(__nv_bfloat162*)(ph + i * 4 + 2) = h23;
        *(__nv_bfloat162*)(pl + i * 4)     = l01;
        *(__nv_bfloat162*)(pl + i * 4 + 2) = l23;
    }
}

// ---------------------------------------------------------------------------
// Launch
// ---------------------------------------------------------------------------
extern "C" void kernel_launch(void* const* d_in, const int* in_sizes, int n_in,
                              void* d_out, int out_size)
{
    const float* ctx   = (const float*)d_in[0];
    const float* query = (const float*)d_in[1];
    const int*   mask  = (const int*)d_in[2];
    float* out = (float*)d_out;

    const size_t BTD = (size_t)Bc * Tc * Dc;
    const size_t BTS = (size_t)Bc * Tc * Sc;
    const size_t BSD = (size_t)Bc * Sc * Dc;

    float* expected_out = out;
    float* p_out;
    if ((size_t)out_size >= BTD + BTS) {
        p_out = out + BTD;
    } else {
        void* sp = nullptr;
        cudaGetSymbolAddress(&sp, g_p_scratch);
        p_out = (float*)sp;
    }

    void *pChi, *pClo, *pQhi, *pQlo, *pPhi, *pPlo;
    cudaGetSymbolAddress(&pChi, g_Chi);
    cudaGetSymbolAddress(&pClo, g_Clo);
    cudaGetSymbolAddress(&pQhi, g_Qhi);
    cudaGetSymbolAddress(&pQlo, g_Qlo);
    cudaGetSymbolAddress(&pPhi, g_Phi);
    cudaGetSymbolAddress(&pPlo, g_Plo);

    cudaFuncSetAttribute(gemm_hmma<Dc, true>,  cudaFuncAttributeMaxDynamicSharedMemorySize, SMEM_TOTAL);
    cudaFuncSetAttribute(gemm_hmma<Sc, false>, cudaFuncAttributeMaxDynamicSharedMemorySize, SMEM_TOTAL);

    // 1. Converts (pure streaming)
    convert_C_kernel<<<(unsigned)(BSD / 4 / 256), 256>>>(ctx);
    convert_Q_kernel<<<(unsigned)(BTD / 4 / 256), 256>>>(query);

    // 2. QK^T -> masked scaled scores into p buffer
    gemm_hmma<Dc, true><<<dim3(Sc / 128, Tc / 128, Bc), 256, SMEM_TOTAL>>>(
        (const __nv_bfloat16*)pQhi, (const __nv_bfloat16*)pQlo,
        (const __nv_bfloat16*)pChi, (const __nv_bfloat16*)pClo,
        mask, p_out, Dc, Dc, Sc, (size_t)Tc * Dc, (size_t)Sc * Dc, (size_t)Tc * Sc);

    // 3. Softmax (fused bf16 hi/lo emit of P)
    softmax_kernel<<<Bc * Tc, 256>>>(p_out);

    // 4. P @ C -> expected_ctx (B = natural-layout C via trans ldmatrix)
    gemm_hmma<Sc, false><<<dim3(Dc / 128, Tc / 128, Bc), 256, SMEM_TOTAL>>>(
        (const __nv_bfloat16*)pPhi, (const __nv_bfloat16*)pPlo,
        (const __nv_bfloat16*)pChi, (const __nv_bfloat16*)pClo,
        nullptr, expected_out, Sc, Dc, Dc, (size_t)Tc * Sc, (size_t)Sc * Dc, (size_t)Tc * Dc);
}

// round 9
// speedup vs baseline: 1.0336x; 1.0336x over previous
#include <cuda_runtime.h>
#include <cuda_bf16.h>
#include <math.h>
#include <stdint.h>

// Problem dims (fixed by dataset)
#define Bc 8
#define Sc 4096
#define Tc 512
#define Dc 1024
#define NEG_NUM -10000.0f

// ---------------------------------------------------------------------------
// Scratch (device globals; no allocations allowed)
// ---------------------------------------------------------------------------
__device__ __nv_bfloat16 g_Chi [(size_t)Bc * Sc * Dc];
__device__ __nv_bfloat16 g_Clo [(size_t)Bc * Sc * Dc];
__device__ __nv_bfloat16 g_Cthi[(size_t)Bc * Dc * Sc];
__device__ __nv_bfloat16 g_Ctlo[(size_t)Bc * Dc * Sc];
__device__ __nv_bfloat16 g_Qhi [(size_t)Bc * Tc * Dc];
__device__ __nv_bfloat16 g_Qlo [(size_t)Bc * Tc * Dc];
__device__ __nv_bfloat16 g_Phi [(size_t)Bc * Tc * Sc];
__device__ __nv_bfloat16 g_Plo [(size_t)Bc * Tc * Sc];
__device__ float         g_p_scratch[(size_t)Bc * Tc * Sc];

// ---------------------------------------------------------------------------
// PTX helpers (baseline PTX only: cp.async, ldmatrix, mma.sync)
// ---------------------------------------------------------------------------
__device__ __forceinline__ uint32_t smem_u32(const void* p) {
    uint32_t a;
    asm("{ .reg .u64 t; cvta.to.shared.u64 t, %1; cvt.u32.u64 %0, t; }" : "=r"(a) : "l"(p));
    return a;
}

__device__ __forceinline__ void cp_async16(uint32_t dst, const void* src) {
    asm volatile("cp.async.cg.shared.global [%0], [%1], 16;" :: "r"(dst), "l"(src));
}
#define CP_COMMIT() asm volatile("cp.async.commit_group;" ::: "memory")
#define CP_WAIT2()  asm volatile("cp.async.wait_group 2;"  ::: "memory")

__device__ __forceinline__ void ldsm_x4(uint32_t* r, uint32_t addr) {
    asm volatile("ldmatrix.sync.aligned.m8n8.x4.shared.b16 {%0,%1,%2,%3}, [%4];"
                 : "=r"(r[0]), "=r"(r[1]), "=r"(r[2]), "=r"(r[3]) : "r"(addr));
}
__device__ __forceinline__ void mma16816(float* d, const uint32_t* a, uint32_t b0, uint32_t b1) {
    asm volatile(
        "mma.sync.aligned.m16n8k16.row.col.f32.bf16.bf16.f32 "
        "{%0,%1,%2,%3}, {%4,%5,%6,%7}, {%8,%9}, {%0,%1,%2,%3};"
        : "+f"(d[0]), "+f"(d[1]), "+f"(d[2]), "+f"(d[3])
        : "r"(a[0]), "r"(a[1]), "r"(a[2]), "r"(a[3]), "r"(b0), "r"(b1));
}

// smem layout (dynamic): [0,512) mask | [1024, +3*64KB) stages
#define SM_MASK    0
#define SM_STAGE0  1024
#define TILE_BYTES_ 16384          // 128 rows x 128B (64 bf16)
#define STAGE_BYTES 65536          // Ahi, Alo, Bhi, Blo
#define SMEM_TOTAL (SM_STAGE0 + 3 * STAGE_BYTES)   // 197632

// SW128 swizzle restricted to our geometry: offset = r*128 + c (c < 128)
// -> swizzled = r*128 + (c ^ ((r & 7) << 4))

// ---------------------------------------------------------------------------
// bf16x3 split GEMM via mma.sync: D[m,n] = sum_k A[m,k]*B[n,k]
// CTA tile 128x128, 8 warps (2x4), warp tile 64x32, BK=64, 3-stage cp.async.
// Both operands stored [row][k] with 128B rows, non-trans ldmatrix.
// ---------------------------------------------------------------------------
template <int KTOT, bool IS_QK>
__global__ __launch_bounds__(256, 1) void gemm_hmma(
    const __nv_bfloat16* __restrict__ Ahi, const __nv_bfloat16* __restrict__ Alo,
    const __nv_bfloat16* __restrict__ Bhi, const __nv_bfloat16* __restrict__ Blo,
    const int* __restrict__ mask, float* __restrict__ Out,
    int lda, int ldb, int ldo, size_t strA, size_t strB, size_t strO)
{
    extern __shared__ __align__(1024) char smem[];
    const uint32_t sb  = smem_u32(smem);
    const int tid  = threadIdx.x;
    const int lane = tid & 31;
    const int wid  = tid >> 5;
    const int wm   = wid & 1;        // 2 warp-rows of 64
    const int wn   = wid >> 1;       // 4 warp-cols of 32
    const int b    = blockIdx.z;
    const int n0   = blockIdx.x * 128;
    const int m0   = blockIdx.y * 128;
    constexpr int NST = KTOT / 64;

    int* smask = (int*)(smem + SM_MASK);
    if (IS_QK && tid < 128) smask[tid] = mask[b * Sc + n0 + tid];

    // ---- cp.async load geometry (16 loads / thread / stage) ----
    uint32_t swz[4];
    size_t   ga[4], gb[4];
#pragma unroll
    for (int j = 0; j < 4; j++) {
        int within = tid + 256 * j;
        int row = within >> 3;
        int u   = within & 7;
        uint32_t off = (uint32_t)(row * 128 + u * 16);
        swz[j] = off ^ ((off >> 3) & 0x70);
        ga[j]  = (size_t)(m0 + row) * lda + u * 8;
        gb[j]  = (size_t)(n0 + row) * ldb + u * 8;
    }
    const __nv_bfloat16* Ah = Ahi + (size_t)b * strA;
    const __nv_bfloat16* Al = Alo + (size_t)b * strA;
    const __nv_bfloat16* Bh = Bhi + (size_t)b * strB;
    const __nv_bfloat16* Bl = Blo + (size_t)b * strB;

    auto load_stage = [&](int k) {
        const uint32_t stg = sb + SM_STAGE0 + (k % 3) * STAGE_BYTES;
        const int kelt = k * 64;
#pragma unroll
        for (int j = 0; j < 4; j++) {
            cp_async16(stg + 0 * TILE_BYTES_ + swz[j], Ah + ga[j] + kelt);
            cp_async16(stg + 1 * TILE_BYTES_ + swz[j], Al + ga[j] + kelt);
            cp_async16(stg + 2 * TILE_BYTES_ + swz[j], Bh + gb[j] + kelt);
            cp_async16(stg + 3 * TILE_BYTES_ + swz[j], Bl + gb[j] + kelt);
        }
    };

    // ---- ldmatrix lane addressing (within-tile offsets) ----
    uint32_t apart[4], aswz[4];
#pragma unroll
    for (int mt = 0; mt < 4; mt++) {
        int r = wm * 64 + mt * 16 + (lane & 15);
        apart[mt] = (uint32_t)r * 128;
        aswz[mt]  = (uint32_t)((r & 7) << 4);
    }
    const uint32_t acol = (uint32_t)((lane >> 4) * 16);
    uint32_t bpart[2], bswz[2];
    {
        int g  = lane >> 3;
        int lr = lane & 7;
        int j  = g >> 1;
#pragma unroll
        for (int p = 0; p < 2; p++) {
            int r = wn * 32 + p * 16 + j * 8 + lr;
            bpart[p] = (uint32_t)r * 128;
            bswz[p]  = (uint32_t)((r & 7) << 4);
        }
    }
    const uint32_t bcol = (uint32_t)((lane >> 3) & 1) * 16;

    float acc[4][4][4];
#pragma unroll
    for (int mt = 0; mt < 4; mt++)
#pragma unroll
        for (int nt = 0; nt < 4; nt++)
#pragma unroll
            for (int f = 0; f < 4; f++) acc[mt][nt][f] = 0.0f;

    // ---- pipeline ----
    load_stage(0); CP_COMMIT();
    load_stage(1); CP_COMMIT();

    for (int k = 0; k < NST; k++) {
        if (k + 2 < NST) load_stage(k + 2);
        CP_COMMIT();
        CP_WAIT2();            // stage k's group retired
        __syncthreads();

        const uint32_t stg = sb + SM_STAGE0 + (k % 3) * STAGE_BYTES;
#pragma unroll
        for (int kk = 0; kk < 64; kk += 16) {
            uint32_t ahi[4][4], alo[4][4], bhi[2][4], blo[2][4];
            const uint32_t ac = (uint32_t)(kk * 2) + acol;
            const uint32_t bc = (uint32_t)(kk * 2) + bcol;
#pragma unroll
            for (int mt = 0; mt < 4; mt++) {
                ldsm_x4(ahi[mt], stg + 0 * TILE_BYTES_ + apart[mt] + (ac ^ aswz[mt]));
                ldsm_x4(alo[mt], stg + 1 * TILE_BYTES_ + apart[mt] + (ac ^ aswz[mt]));
            }
#pragma unroll
            for (int p = 0; p < 2; p++) {
                ldsm_x4(bhi[p], stg + 2 * TILE_BYTES_ + bpart[p] + (bc ^ bswz[p]));
                ldsm_x4(blo[p], stg + 3 * TILE_BYTES_ + bpart[p] + (bc ^ bswz[p]));
            }
#pragma unroll
            for (int mt = 0; mt < 4; mt++)
#pragma unroll
                for (int nt = 0; nt < 4; nt++) {
                    const int p = nt >> 1, o = (nt & 1) * 2;
                    mma16816(acc[mt][nt], ahi[mt], bhi[p][o], bhi[p][o + 1]);
                    mma16816(acc[mt][nt], ahi[mt], blo[p][o], blo[p][o + 1]);
                    mma16816(acc[mt][nt], alo[mt], bhi[p][o], bhi[p][o + 1]);
                }
        }
        __syncthreads();       // all warps done reading stage k (buffer reuse)
    }

    // ---- epilogue ----
    const int r0 = lane >> 2;
    const int c0 = (lane & 3) * 2;
    float* Ob = Out + (size_t)b * strO;
#pragma unroll
    for (int mt = 0; mt < 4; mt++) {
        const int row = m0 + wm * 64 + mt * 16 + r0;
#pragma unroll
        for (int nt = 0; nt < 4; nt++) {
            const int col = n0 + wn * 32 + nt * 8 + c0;
            float* d = acc[mt][nt];
            if (IS_QK) {
                const float scale = 0.03125f;  // 1/sqrt(1024)
                const int mcol = wn * 32 + nt * 8 + c0;
                const int mk0 = smask[mcol], mk1 = smask[mcol + 1];
                float2 v0, v1;
                v0.x = mk0 ? d[0] * scale : NEG_NUM;
                v0.y = mk1 ? d[1] * scale : NEG_NUM;
                v1.x = mk0 ? d[2] * scale : NEG_NUM;
                v1.y = mk1 ? d[3] * scale : NEG_NUM;
                *(float2*)(Ob + (size_t)row * ldo + col)       = v0;
                *(float2*)(Ob + (size_t)(row + 8) * ldo + col) = v1;
            } else {
                *(float2*)(Ob + (size_t)row * ldo + col)       = make_float2(d[0], d[1]);
                *(float2*)(Ob + (size_t)(row + 8) * ldo + col) = make_float2(d[2], d[3]);
            }
        }
    }
}

// ---------------------------------------------------------------------------
// Convert C -> (Chi, Clo) and transposed (Cthi, Ctlo), tiled 32x32
// ---------------------------------------------------------------------------
__global__ __launch_bounds__(256) void convert_C_kernel(const float* __restrict__ C)
{
    __shared__ float tile[32][33];
    const int b  = blockIdx.z;
    const int s0 = blockIdx.y * 32;
    const int d0 = blockIdx.x * 32;
    const int tx = threadIdx.x;   // 0..15
    const int ty = threadIdx.y;   // 0..15

#pragma unroll
    for (int h = 0; h < 2; h++) {
        int r = ty + h * 16;
        size_t gi = ((size_t)b * Sc + s0 + r) * Dc + d0 + 2 * tx;
        float2 v = *(const float2*)(C + gi);
        tile[r][2 * tx]     = v.x;
        tile[r][2 * tx + 1] = v.y;
        __nv_bfloat162 hh = __floats2bfloat162_rn(v.x, v.y);
        float lx = v.x - __bfloat162float(__low2bfloat16(hh));
        float ly = v.y - __bfloat162float(__high2bfloat16(hh));
        __nv_bfloat162 ll = __floats2bfloat162_rn(lx, ly);
        *(__nv_bfloat162*)(g_Chi + gi) = hh;
        *(__nv_bfloat162*)(g_Clo + gi) = ll;
    }
    __syncthreads();
#pragma unroll
    for (int h = 0; h < 2; h++) {
        int dl = ty + h * 16;
        float a0 = tile[2 * tx][dl];
        float a1 = tile[2 * tx + 1][dl];
        size_t go = ((size_t)b * Dc + d0 + dl) * Sc + s0 + 2 * tx;
        __nv_bfloat162 hh = __floats2bfloat162_rn(a0, a1);
        float lx = a0 - __bfloat162float(__low2bfloat16(hh));
        float ly = a1 - __bfloat162float(__high2bfloat16(hh));
        __nv_bfloat162 ll = __floats2bfloat162_rn(lx, ly);
        *(__nv_bfloat162*)(g_Cthi + go) = hh;
        *(__nv_bfloat162*)(g_Ctlo + go) = ll;
    }
}

// ---------------------------------------------------------------------------
// Convert Q -> (Qhi, Qlo)
// ---------------------------------------------------------------------------
__global__ __launch_bounds__(256) void convert_Q_kernel(const float* __restrict__ Q)
{
    size_t i = ((size_t)blockIdx.x * 256 + threadIdx.x) * 4;
    float4 v = *(const float4*)(Q + i);
    __nv_bfloat162 h01 = __floats2bfloat162_rn(v.x, v.y);
    __nv_bfloat162 h23 = __floats2bfloat162_rn(v.z, v.w);
    __nv_bfloat162 l01 = __floats2bfloat162_rn(v.x - __bfloat162float(__low2bfloat16(h01)),
                                               v.y - __bfloat162float(__high2bfloat16(h01)));
    __nv_bfloat162 l23 = __floats2bfloat162_rn(v.z - __bfloat162float(__low2bfloat16(h23)),
                                               v.w - __bfloat162float(__high2bfloat16(h23)));
    *(__nv_bfloat162*)(g_Qhi + i)     = h01;
    *(__nv_bfloat162*)(g_Qhi + i + 2) = h23;
    *(__nv_bfloat162*)(g_Qlo + i)     = l01;
    *(__nv_bfloat162*)(g_Qlo + i + 2) = l23;
}

// ---------------------------------------------------------------------------
// Softmax over S=4096, in place; emits p fp32 + (Phi, Plo) bf16.
// 2 rows per 256-thread block: 128 threads/row, 32 elems/thread (MLP=8),
// 4-warp reductions. Latency-bound fix: double per-thread loads in flight,
// halve barrier width and block count.
// ---------------------------------------------------------------------------
__global__ __launch_bounds__(256) void softmax_kernel(float* __restrict__ P)
{
    const int sub  = threadIdx.x >> 7;                 // which row in block
    const int stid = threadIdx.x & 127;                // thread within row
    const size_t row = (size_t)blockIdx.x * 2 + sub;
    float* p = P + row * Sc;
    const int rwarp = stid >> 5;                       // warp within row (0..3)
    const int lane  = threadIdx.x & 31;
    const int base  = stid * 32;

    __shared__ float red_max[2][4];
    __shared__ float red_sum[2][4];

    float v[32];
#pragma unroll
    for (int i = 0; i < 8; i++) {
        float4 a = *(const float4*)(p + base + i * 4);
        v[i * 4 + 0] = a.x; v[i * 4 + 1] = a.y; v[i * 4 + 2] = a.z; v[i * 4 + 3] = a.w;
    }
    float m = -1e30f;
#pragma unroll
    for (int i = 0; i < 32; i++) m = fmaxf(m, v[i]);
#pragma unroll
    for (int off = 16; off > 0; off >>= 1)
        m = fmaxf(m, __shfl_xor_sync(0xffffffffu, m, off));
    if (lane == 0) red_max[sub][rwarp] = m;
    __syncthreads();
    float bm = fmaxf(fmaxf(red_max[sub][0], red_max[sub][1]),
                     fmaxf(red_max[sub][2], red_max[sub][3]));

    float s = 0.0f;
#pragma unroll
    for (int i = 0; i < 32; i++) { v[i] = __expf(v[i] - bm); s += v[i]; }
#pragma unroll
    for (int off = 16; off > 0; off >>= 1)
        s += __shfl_xor_sync(0xffffffffu, s, off);
    if (lane == 0) red_sum[sub][rwarp] = s;
    __syncthreads();
    const float inv = 1.0f / (red_sum[sub][0] + red_sum[sub][1] +
                              red_sum[sub][2] + red_sum[sub][3]);

    __nv_bfloat16* ph = g_Phi + row * Sc + base;
    __nv_bfloat16* pl = g_Plo + row * Sc + base;
#pragma unroll
    for (int i = 0; i < 8; i++) {
        float4 a;
        a.x = v[i * 4 + 0] * inv; a.y = v[i * 4 + 1] * inv;
        a.z = v[i * 4 + 2] * inv; a.w = v[i * 4 + 3] * inv;
        *(float4*)(p + base + i * 4) = a;
        __nv_bfloat162 h01 = __floats2bfloat162_rn(a.x, a.y);
        __nv_bfloat162 h23 = __floats2bfloat162_rn(a.z, a.w);
        __nv_bfloat162 l01 = __floats2bfloat162_rn(a.x - __bfloat162float(__low2bfloat16(h01)),
                                                   a.y - __bfloat162float(__high2bfloat16(h01)));
        __nv_bfloat162 l23 = __floats2bfloat162_rn(a.z - __bfloat162float(__low2bfloat16(h23)),
                                                   a.w - __bfloat162float(__high2bfloat16(h23)));
        *(__nv_bfloat162*)(ph + i * 4)     = h01;
        *(__nv_bfloat162*)(ph + i * 4 + 2) = h23;
        *(__nv_bfloat162*)(pl + i * 4)     = l01;
        *(__nv_bfloat162*)(pl + i * 4 + 2) = l23;
    }
}

// ---------------------------------------------------------------------------
// Launch
// ---------------------------------------------------------------------------
extern "C" void kernel_launch(void* const* d_in, const int* in_sizes, int n_in,
                              void* d_out, int out_size)
{
    const float* ctx   = (const float*)d_in[0];
    const float* query = (const float*)d_in[1];
    const int*   mask  = (const int*)d_in[2];
    float* out = (float*)d_out;

    const size_t BTD = (size_t)Bc * Tc * Dc;
    const size_t BTS = (size_t)Bc * Tc * Sc;

    float* expected_out = out;
    float* p_out;
    if ((size_t)out_size >= BTD + BTS) {
        p_out = out + BTD;
    } else {
        void* sp = nullptr;
        cudaGetSymbolAddress(&sp, g_p_scratch);
        p_out = (float*)sp;
    }

    void *pChi, *pClo, *pCthi, *pCtlo, *pQhi, *pQlo, *pPhi, *pPlo;
    cudaGetSymbolAddress(&pChi,  g_Chi);
    cudaGetSymbolAddress(&pClo,  g_Clo);
    cudaGetSymbolAddress(&pCthi, g_Cthi);
    cudaGetSymbolAddress(&pCtlo, g_Ctlo);
    cudaGetSymbolAddress(&pQhi,  g_Qhi);
    cudaGetSymbolAddress(&pQlo,  g_Qlo);
    cudaGetSymbolAddress(&pPhi,  g_Phi);
    cudaGetSymbolAddress(&pPlo,  g_Plo);

    cudaFuncSetAttribute(gemm_hmma<Dc, true>,  cudaFuncAttributeMaxDynamicSharedMemorySize, SMEM_TOTAL);
    cudaFuncSetAttribute(gemm_hmma<Sc, false>, cudaFuncAttributeMaxDynamicSharedMemorySize, SMEM_TOTAL);

    // 1. Converts
    convert_C_kernel<<<dim3(Dc / 32, Sc / 32, Bc), dim3(16, 16)>>>(ctx);
    convert_Q_kernel<<<(unsigned)(BTD / 4 / 256), 256>>>(query);

    // 2. QK^T -> masked scaled scores into p buffer
    gemm_hmma<Dc, true><<<dim3(Sc / 128, Tc / 128, Bc), 256, SMEM_TOTAL>>>(
        (const __nv_bfloat16*)pQhi, (const __nv_bfloat16*)pQlo,
        (const __nv_bfloat16*)pChi, (const __nv_bfloat16*)pClo,
        mask, p_out, Dc, Dc, Sc, (size_t)Tc * Dc, (size_t)Sc * Dc, (size_t)Tc * Sc);

    // 3. Softmax (fused bf16 hi/lo emit of P), 2 rows/block
    softmax_kernel<<<Bc * Tc / 2, 256>>>(p_out);

    // 4. P @ C^T(stored K-major) -> expected_ctx
    gemm_hmma<Sc, false><<<dim3(Dc / 128, Tc / 128, Bc), 256, SMEM_TOTAL>>>(
        (const __nv_bfloat16*)pPhi, (const __nv_bfloat16*)pPlo,
        (const __nv_bfloat16*)pCthi, (const __nv_bfloat16*)pCtlo,
        nullptr, expected_out, Sc, Sc, Dc, (size_t)Tc * Sc, (size_t)Dc * Sc, (size_t)Tc * Dc);
}

// round 13
// speedup vs baseline: 1.0534x; 1.0192x over previous
#include <cuda_runtime.h>
#include <cuda_bf16.h>
#include <math.h>
#include <stdint.h>

// Problem dims (fixed by dataset)
#define Bc 8
#define Sc 4096
#define Tc 512
#define Dc 1024
#define NEG_NUM -10000.0f

// ---------------------------------------------------------------------------
// Scratch (device globals; no allocations allowed)
// ---------------------------------------------------------------------------
__device__ __nv_bfloat16 g_Chi [(size_t)Bc * Sc * Dc];
__device__ __nv_bfloat16 g_Clo [(size_t)Bc * Sc * Dc];
__device__ __nv_bfloat16 g_Cthi[(size_t)Bc * Dc * Sc];
__device__ __nv_bfloat16 g_Ctlo[(size_t)Bc * Dc * Sc];
__device__ __nv_bfloat16 g_Qhi [(size_t)Bc * Tc * Dc];
__device__ __nv_bfloat16 g_Qlo [(size_t)Bc * Tc * Dc];
__device__ __nv_bfloat16 g_Phi [(size_t)Bc * Tc * Sc];
__device__ __nv_bfloat16 g_Plo [(size_t)Bc * Tc * Sc];
__device__ float         g_psum[(size_t)Bc * Tc * 32];   // per-row exp-sum partials (32 s-tiles)
__device__ float         g_p_scratch[(size_t)Bc * Tc * Sc];

// ---------------------------------------------------------------------------
// PTX helpers (baseline PTX only: cp.async, ldmatrix, mma.sync)
// ---------------------------------------------------------------------------
__device__ __forceinline__ uint32_t smem_u32(const void* p) {
    uint32_t a;
    asm("{ .reg .u64 t; cvta.to.shared.u64 t, %1; cvt.u32.u64 %0, t; }" : "=r"(a) : "l"(p));
    return a;
}

__device__ __forceinline__ void cp_async16(uint32_t dst, const void* src) {
    asm volatile("cp.async.cg.shared.global [%0], [%1], 16;" :: "r"(dst), "l"(src));
}
#define CP_COMMIT() asm volatile("cp.async.commit_group;" ::: "memory")
#define CP_WAIT2()  asm volatile("cp.async.wait_group 2;"  ::: "memory")

__device__ __forceinline__ void ldsm_x4(uint32_t* r, uint32_t addr) {
    asm volatile("ldmatrix.sync.aligned.m8n8.x4.shared.b16 {%0,%1,%2,%3}, [%4];"
                 : "=r"(r[0]), "=r"(r[1]), "=r"(r[2]), "=r"(r[3]) : "r"(addr));
}
__device__ __forceinline__ void mma16816(float* d, const uint32_t* a, uint32_t b0, uint32_t b1) {
    asm volatile(
        "mma.sync.aligned.m16n8k16.row.col.f32.bf16.bf16.f32 "
        "{%0,%1,%2,%3}, {%4,%5,%6,%7}, {%8,%9}, {%0,%1,%2,%3};"
        : "+f"(d[0]), "+f"(d[1]), "+f"(d[2]), "+f"(d[3])
        : "r"(a[0]), "r"(a[1]), "r"(a[2]), "r"(a[3]), "r"(b0), "r"(b1));
}

// smem layout (dynamic): [0,512) mask | [512,2560) row sums | [4096, +3*64KB) stages
#define SM_MASK    0
#define SM_SUMS    512
#define SM_STAGE0  4096
#define TILE_BYTES_ 16384          // 128 rows x 128B (64 bf16)
#define STAGE_BYTES 65536          // Ahi, Alo, Bhi, Blo
#define SMEM_TOTAL (SM_STAGE0 + 3 * STAGE_BYTES)   // 200704

// SW128 swizzle restricted to our geometry: offset = r*128 + c (c < 128)
// -> swizzled = r*128 + (c ^ ((r & 7) << 4))

// ---------------------------------------------------------------------------
// bf16x3 split GEMM via mma.sync: D[m,n] = sum_k A[m,k]*B[n,k]
// CTA tile 128x128, 8 warps (2x4), warp tile 64x32, BK=64, 3-stage cp.async.
// IS_QK additionally: mask+scale epilogue, per-row exp-sum partials -> g_psum.
// ---------------------------------------------------------------------------
template <int KTOT, bool IS_QK>
__global__ __launch_bounds__(256, 1) void gemm_hmma(
    const __nv_bfloat16* __restrict__ Ahi, const __nv_bfloat16* __restrict__ Alo,
    const __nv_bfloat16* __restrict__ Bhi, const __nv_bfloat16* __restrict__ Blo,
    const int* __restrict__ mask, float* __restrict__ Out,
    int lda, int ldb, int ldo, size_t strA, size_t strB, size_t strO)
{
    extern __shared__ __align__(1024) char smem[];
    const uint32_t sb  = smem_u32(smem);
    const int tid  = threadIdx.x;
    const int lane = tid & 31;
    const int wid  = tid >> 5;
    const int wm   = wid & 1;        // 2 warp-rows of 64
    const int wn   = wid >> 1;       // 4 warp-cols of 32
    const int b    = blockIdx.z;
    const int n0   = blockIdx.x * 128;
    const int m0   = blockIdx.y * 128;
    constexpr int NST = KTOT / 64;

    int* smask = (int*)(smem + SM_MASK);
    if (IS_QK && tid < 128) smask[tid] = mask[b * Sc + n0 + tid];

    // ---- cp.async load geometry (16 loads / thread / stage) ----
    uint32_t swz[4];
    size_t   ga[4], gb[4];
#pragma unroll
    for (int j = 0; j < 4; j++) {
        int within = tid + 256 * j;
        int row = within >> 3;
        int u   = within & 7;
        uint32_t off = (uint32_t)(row * 128 + u * 16);
        swz[j] = off ^ ((off >> 3) & 0x70);
        ga[j]  = (size_t)(m0 + row) * lda + u * 8;
        gb[j]  = (size_t)(n0 + row) * ldb + u * 8;
    }
    const __nv_bfloat16* Ah = Ahi + (size_t)b * strA;
    const __nv_bfloat16* Al = Alo + (size_t)b * strA;
    const __nv_bfloat16* Bh = Bhi + (size_t)b * strB;
    const __nv_bfloat16* Bl = Blo + (size_t)b * strB;

    auto load_stage = [&](int k) {
        const uint32_t stg = sb + SM_STAGE0 + (k % 3) * STAGE_BYTES;
        const int kelt = k * 64;
#pragma unroll
        for (int j = 0; j < 4; j++) {
            cp_async16(stg + 0 * TILE_BYTES_ + swz[j], Ah + ga[j] + kelt);
            cp_async16(stg + 1 * TILE_BYTES_ + swz[j], Al + ga[j] + kelt);
            cp_async16(stg + 2 * TILE_BYTES_ + swz[j], Bh + gb[j] + kelt);
            cp_async16(stg + 3 * TILE_BYTES_ + swz[j], Bl + gb[j] + kelt);
        }
    };

    // ---- ldmatrix lane addressing (within-tile offsets) ----
    uint32_t apart[4], aswz[4];
#pragma unroll
    for (int mt = 0; mt < 4; mt++) {
        int r = wm * 64 + mt * 16 + (lane & 15);
        apart[mt] = (uint32_t)r * 128;
        aswz[mt]  = (uint32_t)((r & 7) << 4);
    }
    const uint32_t acol = (uint32_t)((lane >> 4) * 16);
    uint32_t bpart[2], bswz[2];
    {
        int g  = lane >> 3;
        int lr = lane & 7;
        int j  = g >> 1;
#pragma unroll
        for (int p = 0; p < 2; p++) {
            int r = wn * 32 + p * 16 + j * 8 + lr;
            bpart[p] = (uint32_t)r * 128;
            bswz[p]  = (uint32_t)((r & 7) << 4);
        }
    }
    const uint32_t bcol = (uint32_t)((lane >> 3) & 1) * 16;

    float acc[4][4][4];
#pragma unroll
    for (int mt = 0; mt < 4; mt++)
#pragma unroll
        for (int nt = 0; nt < 4; nt++)
#pragma unroll
            for (int f = 0; f < 4; f++) acc[mt][nt][f] = 0.0f;

    // ---- pipeline ----
    load_stage(0); CP_COMMIT();
    load_stage(1); CP_COMMIT();

    for (int k = 0; k < NST; k++) {
        if (k + 2 < NST) load_stage(k + 2);
        CP_COMMIT();
        CP_WAIT2();            // stage k's group retired
        __syncthreads();

        const uint32_t stg = sb + SM_STAGE0 + (k % 3) * STAGE_BYTES;
#pragma unroll
        for (int kk = 0; kk < 64; kk += 16) {
            uint32_t ahi[4][4], alo[4][4], bhi[2][4], blo[2][4];
            const uint32_t ac = (uint32_t)(kk * 2) + acol;
            const uint32_t bc = (uint32_t)(kk * 2) + bcol;
#pragma unroll
            for (int mt = 0; mt < 4; mt++) {
                ldsm_x4(ahi[mt], stg + 0 * TILE_BYTES_ + apart[mt] + (ac ^ aswz[mt]));
                ldsm_x4(alo[mt], stg + 1 * TILE_BYTES_ + apart[mt] + (ac ^ aswz[mt]));
            }
#pragma unroll
            for (int p = 0; p < 2; p++) {
                ldsm_x4(bhi[p], stg + 2 * TILE_BYTES_ + bpart[p] + (bc ^ bswz[p]));
                ldsm_x4(blo[p], stg + 3 * TILE_BYTES_ + bpart[p] + (bc ^ bswz[p]));
            }
#pragma unroll
            for (int mt = 0; mt < 4; mt++)
#pragma unroll
                for (int nt = 0; nt < 4; nt++) {
                    const int p = nt >> 1, o = (nt & 1) * 2;
                    mma16816(acc[mt][nt], ahi[mt], bhi[p][o], bhi[p][o + 1]);
                    mma16816(acc[mt][nt], ahi[mt], blo[p][o], blo[p][o + 1]);
                    mma16816(acc[mt][nt], alo[mt], bhi[p][o], bhi[p][o + 1]);
                }
        }
        __syncthreads();       // all warps done reading stage k (buffer reuse)
    }

    // ---- epilogue ----
    const int r0 = lane >> 2;
    const int c0 = (lane & 3) * 2;
    float* Ob = Out + (size_t)b * strO;

    if (IS_QK) {
        const float scale = 0.03125f;  // 1/sqrt(1024)
        float rs[4][2];
#pragma unroll
        for (int mt = 0; mt < 4; mt++) { rs[mt][0] = 0.0f; rs[mt][1] = 0.0f; }

#pragma unroll
        for (int mt = 0; mt < 4; mt++) {
            const int row = m0 + wm * 64 + mt * 16 + r0;
#pragma unroll
            for (int nt = 0; nt < 4; nt++) {
                const int col = n0 + wn * 32 + nt * 8 + c0;
                const int mcol = wn * 32 + nt * 8 + c0;
                const int mk0 = smask[mcol], mk1 = smask[mcol + 1];
                float* d = acc[mt][nt];
                float2 v0, v1;
                v0.x = mk0 ? d[0] * scale : NEG_NUM;
                v0.y = mk1 ? d[1] * scale : NEG_NUM;
                v1.x = mk0 ? d[2] * scale : NEG_NUM;
                v1.y = mk1 ? d[3] * scale : NEG_NUM;
                *(float2*)(Ob + (size_t)row * ldo + col)       = v0;
                *(float2*)(Ob + (size_t)(row + 8) * ldo + col) = v1;
                rs[mt][0] += __expf(v0.x) + __expf(v0.y);
                rs[mt][1] += __expf(v1.x) + __expf(v1.y);
            }
        }
        // reduce across the 4 lanes sharing a row (lane&3), deterministic order
        float* ssum = (float*)(smem + SM_SUMS);   // [128 rows][4 warp-cols]
#pragma unroll
        for (int mt = 0; mt < 4; mt++)
#pragma unroll
            for (int half = 0; half < 2; half++) {
                float r = rs[mt][half];
                r += __shfl_xor_sync(0xffffffffu, r, 1);
                r += __shfl_xor_sync(0xffffffffu, r, 2);
                if ((lane & 3) == 0) {
                    int rloc = wm * 64 + mt * 16 + half * 8 + r0;
                    ssum[rloc * 4 + wn] = r;
                }
            }
        __syncthreads();
        if (tid < 128) {
            float t = ssum[tid * 4 + 0] + ssum[tid * 4 + 1]
                    + ssum[tid * 4 + 2] + ssum[tid * 4 + 3];
            g_psum[((size_t)b * Tc + m0 + tid) * 32 + blockIdx.x] = t;
        }
    } else {
#pragma unroll
        for (int mt = 0; mt < 4; mt++) {
            const int row = m0 + wm * 64 + mt * 16 + r0;
#pragma unroll
            for (int nt = 0; nt < 4; nt++) {
                const int col = n0 + wn * 32 + nt * 8 + c0;
                float* d = acc[mt][nt];
                *(float2*)(Ob + (size_t)row * ldo + col)       = make_float2(d[0], d[1]);
                *(float2*)(Ob + (size_t)(row + 8) * ldo + col) = make_float2(d[2], d[3]);
            }
        }
    }
}

// ---------------------------------------------------------------------------
// Convert C -> (Chi, Clo) and transposed (Cthi, Ctlo), tiled 32x32
// ---------------------------------------------------------------------------
__global__ __launch_bounds__(256) void convert_C_kernel(const float* __restrict__ C)
{
    __shared__ float tile[32][33];
    const int b  = blockIdx.z;
    const int s0 = blockIdx.y * 32;
    const int d0 = blockIdx.x * 32;
    const int tx = threadIdx.x;   // 0..15
    const int ty = threadIdx.y;   // 0..15

#pragma unroll
    for (int h = 0; h < 2; h++) {
        int r = ty + h * 16;
        size_t gi = ((size_t)b * Sc + s0 + r) * Dc + d0 + 2 * tx;
        float2 v = *(const float2*)(C + gi);
        tile[r][2 * tx]     = v.x;
        tile[r][2 * tx + 1] = v.y;
        __nv_bfloat162 hh = __floats2bfloat162_rn(v.x, v.y);
        float lx = v.x - __bfloat162float(__low2bfloat16(hh));
        float ly = v.y - __bfloat162float(__high2bfloat16(hh));
        __nv_bfloat162 ll = __floats2bfloat162_rn(lx, ly);
        *(__nv_bfloat162*)(g_Chi + gi) = hh;
        *(__nv_bfloat162*)(g_Clo + gi) = ll;
    }
    __syncthreads();
#pragma unroll
    for (int h = 0; h < 2; h++) {
        int dl = ty + h * 16;
        float a0 = tile[2 * tx][dl];
        float a1 = tile[2 * tx + 1][dl];
        size_t go = ((size_t)b * Dc + d0 + dl) * Sc + s0 + 2 * tx;
        __nv_bfloat162 hh = __floats2bfloat162_rn(a0, a1);
        float lx = a0 - __bfloat162float(__low2bfloat16(hh));
        float ly = a1 - __bfloat162float(__high2bfloat16(hh));
        __nv_bfloat162 ll = __floats2bfloat162_rn(lx, ly);
        *(__nv_bfloat162*)(g_Cthi + go) = hh;
        *(__nv_bfloat162*)(g_Ctlo + go) = ll;
    }
}

// ---------------------------------------------------------------------------
// Convert Q -> (Qhi, Qlo)
// ---------------------------------------------------------------------------
__global__ __launch_bounds__(256) void convert_Q_kernel(const float* __restrict__ Q)
{
    size_t i = ((size_t)blockIdx.x * 256 + threadIdx.x) * 4;
    float4 v = *(const float4*)(Q + i);
    __nv_bfloat162 h01 = __floats2bfloat162_rn(v.x, v.y);
    __nv_bfloat162 h23 = __floats2bfloat162_rn(v.z, v.w);
    __nv_bfloat162 l01 = __floats2bfloat162_rn(v.x - __bfloat162float(__low2bfloat16(h01)),
                                               v.y - __bfloat162float(__high2bfloat16(h01)));
    __nv_bfloat162 l23 = __floats2bfloat162_rn(v.z - __bfloat162float(__low2bfloat16(h23)),
                                               v.w - __bfloat162float(__high2bfloat16(h23)));
    *(__nv_bfloat162*)(g_Qhi + i)     = h01;
    *(__nv_bfloat162*)(g_Qhi + i + 2) = h23;
    *(__nv_bfloat162*)(g_Qlo + i)     = l01;
    *(__nv_bfloat162*)(g_Qlo + i + 2) = l23;
}

// ---------------------------------------------------------------------------
// Normalize: p = exp(score) / rowsum  (rowsum from g_psum partials).
// No reductions, no barriers: 1 row per 256-thread block, 16 elems/thread.
// Emits p fp32 + (Phi, Plo) bf16.
// ---------------------------------------------------------------------------
__global__ __launch_bounds__(256) void norm_kernel(float* __restrict__ P)
{
    const size_t row = blockIdx.x;
    float* p = P + row * Sc;
    const float* ps = g_psum + row * 32;

    float sum = 0.0f;
#pragma unroll
    for (int i = 0; i < 32; i++) sum += ps[i];   // warp-uniform broadcast loads
    const float inv = 1.0f / sum;

    const int base = threadIdx.x * 16;
    __nv_bfloat16* ph = g_Phi + row * Sc + base;
    __nv_bfloat16* pl = g_Plo + row * Sc + base;
#pragma unroll
    for (int i = 0; i < 4; i++) {
        float4 a = *(const float4*)(p + base + i * 4);
        a.x = __expf(a.x) * inv; a.y = __expf(a.y) * inv;
        a.z = __expf(a.z) * inv; a.w = __expf(a.w) * inv;
        *(float4*)(p + base + i * 4) = a;
        __nv_bfloat162 h01 = __floats2bfloat162_rn(a.x, a.y);
        __nv_bfloat162 h23 = __floats2bfloat162_rn(a.z, a.w);
        __nv_bfloat162 l01 = __floats2bfloat162_rn(a.x - __bfloat162float(__low2bfloat16(h01)),
                                                   a.y - __bfloat162float(__high2bfloat16(h01)));
        __nv_bfloat162 l23 = __floats2bfloat162_rn(a.z - __bfloat162float(__low2bfloat16(h23)),
                                                   a.w - __bfloat162float(__high2bfloat16(h23)));
        *(__nv_bfloat162*)(ph + i * 4)     = h01;
        *(__nv_bfloat162*)(ph + i * 4 + 2) = h23;
        *(__nv_bfloat162*)(pl + i * 4)     = l01;
        *(__nv_bfloat162*)(pl + i * 4 + 2) = l23;
    }
}

// ---------------------------------------------------------------------------
// Launch
// ---------------------------------------------------------------------------
extern "C" void kernel_launch(void* const* d_in, const int* in_sizes, int n_in,
                              void* d_out, int out_size)
{
    const float* ctx   = (const float*)d_in[0];
    const float* query = (const float*)d_in[1];
    const int*   mask  = (const int*)d_in[2];
    float* out = (float*)d_out;

    const size_t BTD = (size_t)Bc * Tc * Dc;
    const size_t BTS = (size_t)Bc * Tc * Sc;

    float* expected_out = out;
    float* p_out;
    if ((size_t)out_size >= BTD + BTS) {
        p_out = out + BTD;
    } else {
        void* sp = nullptr;
        cudaGetSymbolAddress(&sp, g_p_scratch);
        p_out = (float*)sp;
    }

    void *pChi, *pClo, *pCthi, *pCtlo, *pQhi, *pQlo, *pPhi, *pPlo;
    cudaGetSymbolAddress(&pChi,  g_Chi);
    cudaGetSymbolAddress(&pClo,  g_Clo);
    cudaGetSymbolAddress(&pCthi, g_Cthi);
    cudaGetSymbolAddress(&pCtlo, g_Ctlo);
    cudaGetSymbolAddress(&pQhi,  g_Qhi);
    cudaGetSymbolAddress(&pQlo,  g_Qlo);
    cudaGetSymbolAddress(&pPhi,  g_Phi);
    cudaGetSymbolAddress(&pPlo,  g_Plo);

    cudaFuncSetAttribute(gemm_hmma<Dc, true>,  cudaFuncAttributeMaxDynamicSharedMemorySize, SMEM_TOTAL);
    cudaFuncSetAttribute(gemm_hmma<Sc, false>, cudaFuncAttributeMaxDynamicSharedMemorySize, SMEM_TOTAL);

    // 1. Converts
    convert_C_kernel<<<dim3(Dc / 32, Sc / 32, Bc), dim3(16, 16)>>>(ctx);
    convert_Q_kernel<<<(unsigned)(BTD / 4 / 256), 256>>>(query);

    // 2. QK^T -> masked scaled scores + per-row exp-sum partials
    gemm_hmma<Dc, true><<<dim3(Sc / 128, Tc / 128, Bc), 256, SMEM_TOTAL>>>(
        (const __nv_bfloat16*)pQhi, (const __nv_bfloat16*)pQlo,
        (const __nv_bfloat16*)pChi, (const __nv_bfloat16*)pClo,
        mask, p_out, Dc, Dc, Sc, (size_t)Tc * Dc, (size_t)Sc * Dc, (size_t)Tc * Sc);

    // 3. Reduction-free normalize (fused bf16 hi/lo emit of P)
    norm_kernel<<<Bc * Tc, 256>>>(p_out);

    // 4. P @ C^T(stored K-major) -> expected_ctx
    gemm_hmma<Sc, false><<<dim3(Dc / 128, Tc / 128, Bc), 256, SMEM_TOTAL>>>(
        (const __nv_bfloat16*)pPhi, (const __nv_bfloat16*)pPlo,
        (const __nv_bfloat16*)pCthi, (const __nv_bfloat16*)pCtlo,
        nullptr, expected_out, Sc, Sc, Dc, (size_t)Tc * Sc, (size_t)Dc * Sc, (size_t)Tc * Dc);
}

// round 14
// speedup vs baseline: 1.0879x; 1.0328x over previous
#include <cuda_runtime.h>
#include <cuda_bf16.h>
#include <math.h>
#include <stdint.h>

// Problem dims (fixed by dataset)
#define Bc 8
#define Sc 4096
#define Tc 512
#define Dc 1024
#define NEG_NUM -10000.0f

// ---------------------------------------------------------------------------
// Scratch (device globals; no allocations allowed)
// ---------------------------------------------------------------------------
__device__ __nv_bfloat16 g_Chi [(size_t)Bc * Sc * Dc];
__device__ __nv_bfloat16 g_Clo [(size_t)Bc * Sc * Dc];
__device__ __nv_bfloat16 g_Cthi[(size_t)Bc * Dc * Sc];
__device__ __nv_bfloat16 g_Ctlo[(size_t)Bc * Dc * Sc];
__device__ __nv_bfloat16 g_Qhi [(size_t)Bc * Tc * Dc];
__device__ __nv_bfloat16 g_Qlo [(size_t)Bc * Tc * Dc];
__device__ __nv_bfloat16 g_Ehi [(size_t)Bc * Tc * Sc];   // unnormalized exp(score), hi
__device__ __nv_bfloat16 g_Elo [(size_t)Bc * Tc * Sc];   // unnormalized exp(score), lo
__device__ float         g_psum[(size_t)Bc * Tc * 32];   // per-row exp-sum partials
__device__ float         g_inv [(size_t)Bc * Tc];        // 1 / rowsum
__device__ float         g_p_scratch[(size_t)Bc * Tc * Sc];

// ---------------------------------------------------------------------------
// PTX helpers (baseline PTX only: cp.async, ldmatrix, mma.sync)
// ---------------------------------------------------------------------------
__device__ __forceinline__ uint32_t smem_u32(const void* p) {
    uint32_t a;
    asm("{ .reg .u64 t; cvta.to.shared.u64 t, %1; cvt.u32.u64 %0, t; }" : "=r"(a) : "l"(p));
    return a;
}

__device__ __forceinline__ void cp_async16(uint32_t dst, const void* src) {
    asm volatile("cp.async.cg.shared.global [%0], [%1], 16;" :: "r"(dst), "l"(src));
}
#define CP_COMMIT() asm volatile("cp.async.commit_group;" ::: "memory")
#define CP_WAIT2()  asm volatile("cp.async.wait_group 2;"  ::: "memory")

__device__ __forceinline__ void ldsm_x4(uint32_t* r, uint32_t addr) {
    asm volatile("ldmatrix.sync.aligned.m8n8.x4.shared.b16 {%0,%1,%2,%3}, [%4];"
                 : "=r"(r[0]), "=r"(r[1]), "=r"(r[2]), "=r"(r[3]) : "r"(addr));
}
__device__ __forceinline__ void mma16816(float* d, const uint32_t* a, uint32_t b0, uint32_t b1) {
    asm volatile(
        "mma.sync.aligned.m16n8k16.row.col.f32.bf16.bf16.f32 "
        "{%0,%1,%2,%3}, {%4,%5,%6,%7}, {%8,%9}, {%0,%1,%2,%3};"
        : "+f"(d[0]), "+f"(d[1]), "+f"(d[2]), "+f"(d[3])
        : "r"(a[0]), "r"(a[1]), "r"(a[2]), "r"(a[3]), "r"(b0), "r"(b1));
}

// smem layout (dynamic): [0,512) mask | [512,2560) row sums | [4096, +3*32KB) stages
#define SM_MASK    0
#define SM_SUMS    512
#define SM_STAGE0  4096
#define TILE_BYTES_ 8192           // 128 rows x 64B (32 bf16)
#define STAGE_BYTES 32768          // Ahi, Alo, Bhi, Blo
#define SMEM_TOTAL (SM_STAGE0 + 3 * STAGE_BYTES)   // 102400 -> 2 CTAs/SM

// 64B-row swizzle: addr = r*64 + (c ^ (((r>>1)&3)<<4)), c in {0,16,32,48}
// (half = r&1 via the *64 row stride, chunk = c^((r>>1)&3) -> bijective, conflict-free)

// ---------------------------------------------------------------------------
// bf16x3 split GEMM via mma.sync: acc[m,n] = sum_k A[m,k]*B[n,k]
// CTA tile 128x128, 8 warps (2x4), warp tile 64x32, BK=32, 3-stage cp.async,
// 2 CTAs/SM. IS_QK: epilogue computes E=exp(mask(score*scale)), stores E as
// bf16 hi/lo + per-row partial sums. Else: scales output rows by g_inv.
// ---------------------------------------------------------------------------
template <int KTOT, bool IS_QK>
__global__ __launch_bounds__(256, 2) void gemm_hmma(
    const __nv_bfloat16* __restrict__ Ahi, const __nv_bfloat16* __restrict__ Alo,
    const __nv_bfloat16* __restrict__ Bhi, const __nv_bfloat16* __restrict__ Blo,
    const int* __restrict__ mask, float* __restrict__ Out,
    __nv_bfloat16* __restrict__ EOhi, __nv_bfloat16* __restrict__ EOlo,
    int lda, int ldb, int ldo, size_t strA, size_t strB, size_t strO)
{
    extern __shared__ __align__(1024) char smem[];
    const uint32_t sb  = smem_u32(smem);
    const int tid  = threadIdx.x;
    const int lane = tid & 31;
    const int wid  = tid >> 5;
    const int wm   = wid & 1;        // 2 warp-rows of 64
    const int wn   = wid >> 1;       // 4 warp-cols of 32
    const int b    = blockIdx.z;
    const int n0   = blockIdx.x * 128;
    const int m0   = blockIdx.y * 128;
    constexpr int NST = KTOT / 32;

    int* smask = (int*)(smem + SM_MASK);
    if (IS_QK && tid < 128) smask[tid] = mask[b * Sc + n0 + tid];

    // ---- cp.async load geometry (8 loads / thread / stage: 2 per tile) ----
    uint32_t swz[2];
    size_t   ga[2], gb[2];
#pragma unroll
    for (int j = 0; j < 2; j++) {
        int within = tid + 256 * j;
        int row = within >> 2;           // 0..127
        int u   = within & 3;            // 16B chunk
        swz[j] = (uint32_t)(row * 64 + ((u * 16) ^ (((row >> 1) & 3) << 4)));
        ga[j]  = (size_t)(m0 + row) * lda + u * 8;
        gb[j]  = (size_t)(n0 + row) * ldb + u * 8;
    }
    const __nv_bfloat16* Ah = Ahi + (size_t)b * strA;
    const __nv_bfloat16* Al = Alo + (size_t)b * strA;
    const __nv_bfloat16* Bh = Bhi + (size_t)b * strB;
    const __nv_bfloat16* Bl = Blo + (size_t)b * strB;

    auto load_stage = [&](int k) {
        const uint32_t stg = sb + SM_STAGE0 + (k % 3) * STAGE_BYTES;
        const int kelt = k * 32;
#pragma unroll
        for (int j = 0; j < 2; j++) {
            cp_async16(stg + 0 * TILE_BYTES_ + swz[j], Ah + ga[j] + kelt);
            cp_async16(stg + 1 * TILE_BYTES_ + swz[j], Al + ga[j] + kelt);
            cp_async16(stg + 2 * TILE_BYTES_ + swz[j], Bh + gb[j] + kelt);
            cp_async16(stg + 3 * TILE_BYTES_ + swz[j], Bl + gb[j] + kelt);
        }
    };

    // ---- ldmatrix lane addressing ----
    uint32_t apart[4], aswz[4];
#pragma unroll
    for (int mt = 0; mt < 4; mt++) {
        int r = wm * 64 + mt * 16 + (lane & 15);
        apart[mt] = (uint32_t)r * 64;
        aswz[mt]  = (uint32_t)(((r >> 1) & 3) << 4);
    }
    const uint32_t acol = (uint32_t)((lane >> 4) * 16);
    uint32_t bpart[2], bswz[2];
    {
        int g  = lane >> 3;
        int lr = lane & 7;
        int j  = g >> 1;
#pragma unroll
        for (int p = 0; p < 2; p++) {
            int r = wn * 32 + p * 16 + j * 8 + lr;
            bpart[p] = (uint32_t)r * 64;
            bswz[p]  = (uint32_t)(((r >> 1) & 3) << 4);
        }
    }
    const uint32_t bcol = (uint32_t)((lane >> 3) & 1) * 16;

    float acc[4][4][4];
#pragma unroll
    for (int mt = 0; mt < 4; mt++)
#pragma unroll
        for (int nt = 0; nt < 4; nt++)
#pragma unroll
            for (int f = 0; f < 4; f++) acc[mt][nt][f] = 0.0f;

    // ---- pipeline ----
    load_stage(0); CP_COMMIT();
    load_stage(1); CP_COMMIT();

    for (int k = 0; k < NST; k++) {
        if (k + 2 < NST) load_stage(k + 2);
        CP_COMMIT();
        CP_WAIT2();            // stage k resident
        __syncthreads();

        const uint32_t stg = sb + SM_STAGE0 + (k % 3) * STAGE_BYTES;
#pragma unroll
        for (int kk = 0; kk < 32; kk += 16) {
            uint32_t ahi[4][4], alo[4][4], bhi[2][4], blo[2][4];
            const uint32_t ac = (uint32_t)(kk * 2) + acol;
            const uint32_t bc = (uint32_t)(kk * 2) + bcol;
#pragma unroll
            for (int mt = 0; mt < 4; mt++) {
                ldsm_x4(ahi[mt], stg + 0 * TILE_BYTES_ + apart[mt] + (ac ^ aswz[mt]));
                ldsm_x4(alo[mt], stg + 1 * TILE_BYTES_ + apart[mt] + (ac ^ aswz[mt]));
            }
#pragma unroll
            for (int p = 0; p < 2; p++) {
                ldsm_x4(bhi[p], stg + 2 * TILE_BYTES_ + bpart[p] + (bc ^ bswz[p]));
                ldsm_x4(blo[p], stg + 3 * TILE_BYTES_ + bpart[p] + (bc ^ bswz[p]));
            }
#pragma unroll
            for (int mt = 0; mt < 4; mt++)
#pragma unroll
                for (int nt = 0; nt < 4; nt++) {
                    const int p = nt >> 1, o = (nt & 1) * 2;
                    mma16816(acc[mt][nt], ahi[mt], bhi[p][o], bhi[p][o + 1]);
                    mma16816(acc[mt][nt], ahi[mt], blo[p][o], blo[p][o + 1]);
                    mma16816(acc[mt][nt], alo[mt], bhi[p][o], bhi[p][o + 1]);
                }
        }
        __syncthreads();       // buffer reuse
    }

    // ---- epilogue ----
    const int r0 = lane >> 2;
    const int c0 = (lane & 3) * 2;

    if (IS_QK) {
        const float scale = 0.03125f;  // 1/sqrt(1024)
        __nv_bfloat16* Eh = EOhi + (size_t)b * strO;
        __nv_bfloat16* El = EOlo + (size_t)b * strO;
        float rs[4][2];
#pragma unroll
        for (int mt = 0; mt < 4; mt++) { rs[mt][0] = 0.0f; rs[mt][1] = 0.0f; }

#pragma unroll
        for (int mt = 0; mt < 4; mt++) {
            const int row = m0 + wm * 64 + mt * 16 + r0;
#pragma unroll
            for (int nt = 0; nt < 4; nt++) {
                const int col = n0 + wn * 32 + nt * 8 + c0;
                const int mcol = wn * 32 + nt * 8 + c0;
                const int mk0 = smask[mcol], mk1 = smask[mcol + 1];
                float* d = acc[mt][nt];
                float e00 = mk0 ? __expf(d[0] * scale) : 0.0f;
                float e01 = mk1 ? __expf(d[1] * scale) : 0.0f;
                float e10 = mk0 ? __expf(d[2] * scale) : 0.0f;
                float e11 = mk1 ? __expf(d[3] * scale) : 0.0f;
                rs[mt][0] += e00 + e01;
                rs[mt][1] += e10 + e11;
                __nv_bfloat162 h0 = __floats2bfloat162_rn(e00, e01);
                __nv_bfloat162 h1 = __floats2bfloat162_rn(e10, e11);
                __nv_bfloat162 l0 = __floats2bfloat162_rn(e00 - __bfloat162float(__low2bfloat16(h0)),
                                                          e01 - __bfloat162float(__high2bfloat16(h0)));
                __nv_bfloat162 l1 = __floats2bfloat162_rn(e10 - __bfloat162float(__low2bfloat16(h1)),
                                                          e11 - __bfloat162float(__high2bfloat16(h1)));
                *(__nv_bfloat162*)(Eh + (size_t)row * ldo + col)       = h0;
                *(__nv_bfloat162*)(Eh + (size_t)(row + 8) * ldo + col) = h1;
                *(__nv_bfloat162*)(El + (size_t)row * ldo + col)       = l0;
                *(__nv_bfloat162*)(El + (size_t)(row + 8) * ldo + col) = l1;
            }
        }
        // reduce across the 4 lanes sharing a row, deterministic order
        float* ssum = (float*)(smem + SM_SUMS);   // [128 rows][4 warp-cols]
#pragma unroll
        for (int mt = 0; mt < 4; mt++)
#pragma unroll
            for (int half = 0; half < 2; half++) {
                float r = rs[mt][half];
                r += __shfl_xor_sync(0xffffffffu, r, 1);
                r += __shfl_xor_sync(0xffffffffu, r, 2);
                if ((lane & 3) == 0) {
                    int rloc = wm * 64 + mt * 16 + half * 8 + r0;
                    ssum[rloc * 4 + wn] = r;
                }
            }
        __syncthreads();
        if (tid < 128) {
            float t = ssum[tid * 4 + 0] + ssum[tid * 4 + 1]
                    + ssum[tid * 4 + 2] + ssum[tid * 4 + 3];
            g_psum[((size_t)b * Tc + m0 + tid) * 32 + blockIdx.x] = t;
        }
    } else {
        float* Ob = Out + (size_t)b * strO;
        const float* invb = g_inv + (size_t)b * Tc;
#pragma unroll
        for (int mt = 0; mt < 4; mt++) {
            const int row = m0 + wm * 64 + mt * 16 + r0;
            const float i0 = invb[row];
            const float i1 = invb[row + 8];
#pragma unroll
            for (int nt = 0; nt < 4; nt++) {
                const int col = n0 + wn * 32 + nt * 8 + c0;
                float* d = acc[mt][nt];
                *(float2*)(Ob + (size_t)row * ldo + col)       = make_float2(d[0] * i0, d[1] * i0);
                *(float2*)(Ob + (size_t)(row + 8) * ldo + col) = make_float2(d[2] * i1, d[3] * i1);
            }
        }
    }
}

// ---------------------------------------------------------------------------
// Convert C -> (Chi, Clo) and transposed (Cthi, Ctlo), tiled 32x32
// ---------------------------------------------------------------------------
__global__ __launch_bounds__(256) void convert_C_kernel(const float* __restrict__ C)
{
    __shared__ float tile[32][33];
    const int b  = blockIdx.z;
    const int s0 = blockIdx.y * 32;
    const int d0 = blockIdx.x * 32;
    const int tx = threadIdx.x;   // 0..15
    const int ty = threadIdx.y;   // 0..15

#pragma unroll
    for (int h = 0; h < 2; h++) {
        int r = ty + h * 16;
        size_t gi = ((size_t)b * Sc + s0 + r) * Dc + d0 + 2 * tx;
        float2 v = *(const float2*)(C + gi);
        tile[r][2 * tx]     = v.x;
        tile[r][2 * tx + 1] = v.y;
        __nv_bfloat162 hh = __floats2bfloat162_rn(v.x, v.y);
        float lx = v.x - __bfloat162float(__low2bfloat16(hh));
        float ly = v.y - __bfloat162float(__high2bfloat16(hh));
        __nv_bfloat162 ll = __floats2bfloat162_rn(lx, ly);
        *(__nv_bfloat162*)(g_Chi + gi) = hh;
        *(__nv_bfloat162*)(g_Clo + gi) = ll;
    }
    __syncthreads();
#pragma unroll
    for (int h = 0; h < 2; h++) {
        int dl = ty + h * 16;
        float a0 = tile[2 * tx][dl];
        float a1 = tile[2 * tx + 1][dl];
        size_t go = ((size_t)b * Dc + d0 + dl) * Sc + s0 + 2 * tx;
        __nv_bfloat162 hh = __floats2bfloat162_rn(a0, a1);
        float lx = a0 - __bfloat162float(__low2bfloat16(hh));
        float ly = a1 - __bfloat162float(__high2bfloat16(hh));
        __nv_bfloat162 ll = __floats2bfloat162_rn(lx, ly);
        *(__nv_bfloat162*)(g_Cthi + go) = hh;
        *(__nv_bfloat162*)(g_Ctlo + go) = ll;
    }
}

// ---------------------------------------------------------------------------
// Convert Q -> (Qhi, Qlo)
// ---------------------------------------------------------------------------
__global__ __launch_bounds__(256) void convert_Q_kernel(const float* __restrict__ Q)
{
    size_t i = ((size_t)blockIdx.x * 256 + threadIdx.x) * 4;
    float4 v = *(const float4*)(Q + i);
    __nv_bfloat162 h01 = __floats2bfloat162_rn(v.x, v.y);
    __nv_bfloat162 h23 = __floats2bfloat162_rn(v.z, v.w);
    __nv_bfloat162 l01 = __floats2bfloat162_rn(v.x - __bfloat162float(__low2bfloat16(h01)),
                                               v.y - __bfloat162float(__high2bfloat16(h01)));
    __nv_bfloat162 l23 = __floats2bfloat162_rn(v.z - __bfloat162float(__low2bfloat16(h23)),
                                               v.w - __bfloat162float(__high2bfloat16(h23)));
    *(__nv_bfloat162*)(g_Qhi + i)     = h01;
    *(__nv_bfloat162*)(g_Qhi + i + 2) = h23;
    *(__nv_bfloat162*)(g_Qlo + i)     = l01;
    *(__nv_bfloat162*)(g_Qlo + i + 2) = l23;
}

// ---------------------------------------------------------------------------
// inv_kernel: g_inv[row] = 1 / sum(g_psum[row][0..31])
// ---------------------------------------------------------------------------
__global__ __launch_bounds__(256) void inv_kernel()
{
    const int row = blockIdx.x * 256 + threadIdx.x;   // 0..Bc*Tc-1
    const float* ps = g_psum + (size_t)row * 32;
    float s = 0.0f;
#pragma unroll
    for (int i = 0; i < 32; i++) s += ps[i];
    g_inv[row] = 1.0f / s;
}

// ---------------------------------------------------------------------------
// pctx_kernel: p_ctx[row][s] = (Ehi + Elo) * g_inv[row]  (pure stream)
// ---------------------------------------------------------------------------
__global__ __launch_bounds__(256) void pctx_kernel(float* __restrict__ P)
{
    const size_t row = blockIdx.x;
    const float inv = g_inv[row];
    const int base = threadIdx.x * 16;
    const __nv_bfloat162* eh = (const __nv_bfloat162*)(g_Ehi + row * Sc + base);
    const __nv_bfloat162* el = (const __nv_bfloat162*)(g_Elo + row * Sc + base);
    float* p = P + row * Sc + base;
#pragma unroll
    for (int i = 0; i < 4; i++) {
        __nv_bfloat162 h0 = eh[i * 2],     h1 = eh[i * 2 + 1];
        __nv_bfloat162 l0 = el[i * 2],     l1 = el[i * 2 + 1];
        float4 a;
        a.x = (__bfloat162float(__low2bfloat16(h0))  + __bfloat162float(__low2bfloat16(l0)))  * inv;
        a.y = (__bfloat162float(__high2bfloat16(h0)) + __bfloat162float(__high2bfloat16(l0))) * inv;
        a.z = (__bfloat162float(__low2bfloat16(h1))  + __bfloat162float(__low2bfloat16(l1)))  * inv;
        a.w = (__bfloat162float(__high2bfloat16(h1)) + __bfloat162float(__high2bfloat16(l1))) * inv;
        *(float4*)(p + i * 4) = a;
    }
}

// ---------------------------------------------------------------------------
// Launch
// ---------------------------------------------------------------------------
extern "C" void kernel_launch(void* const* d_in, const int* in_sizes, int n_in,
                              void* d_out, int out_size)
{
    const float* ctx   = (const float*)d_in[0];
    const float* query = (const float*)d_in[1];
    const int*   mask  = (const int*)d_in[2];
    float* out = (float*)d_out;

    const size_t BTD = (size_t)Bc * Tc * Dc;
    const size_t BTS = (size_t)Bc * Tc * Sc;

    float* expected_out = out;
    float* p_out;
    if ((size_t)out_size >= BTD + BTS) {
        p_out = out + BTD;
    } else {
        void* sp = nullptr;
        cudaGetSymbolAddress(&sp, g_p_scratch);
        p_out = (float*)sp;
    }

    void *pChi, *pClo, *pCthi, *pCtlo, *pQhi, *pQlo, *pEhi, *pElo;
    cudaGetSymbolAddress(&pChi,  g_Chi);
    cudaGetSymbolAddress(&pClo,  g_Clo);
    cudaGetSymbolAddress(&pCthi, g_Cthi);
    cudaGetSymbolAddress(&pCtlo, g_Ctlo);
    cudaGetSymbolAddress(&pQhi,  g_Qhi);
    cudaGetSymbolAddress(&pQlo,  g_Qlo);
    cudaGetSymbolAddress(&pEhi,  g_Ehi);
    cudaGetSymbolAddress(&pElo,  g_Elo);

    cudaFuncSetAttribute(gemm_hmma<Dc, true>,  cudaFuncAttributeMaxDynamicSharedMemorySize, SMEM_TOTAL);
    cudaFuncSetAttribute(gemm_hmma<Sc, false>, cudaFuncAttributeMaxDynamicSharedMemorySize, SMEM_TOTAL);

    // 1. Converts
    convert_C_kernel<<<dim3(Dc / 32, Sc / 32, Bc), dim3(16, 16)>>>(ctx);
    convert_Q_kernel<<<(unsigned)(BTD / 4 / 256), 256>>>(query);

    // 2. QK^T -> E = exp(masked scaled scores) as bf16 hi/lo + row-sum partials
    gemm_hmma<Dc, true><<<dim3(Sc / 128, Tc / 128, Bc), 256, SMEM_TOTAL>>>(
        (const __nv_bfloat16*)pQhi, (const __nv_bfloat16*)pQlo,
        (const __nv_bfloat16*)pChi, (const __nv_bfloat16*)pClo,
        mask, nullptr, (__nv_bfloat16*)pEhi, (__nv_bfloat16*)pElo,
        Dc, Dc, Sc, (size_t)Tc * Dc, (size_t)Sc * Dc, (size_t)Tc * Sc);

    // 3. Row sums -> inverses; p_ctx output stream
    inv_kernel<<<Bc * Tc / 256, 256>>>();
    pctx_kernel<<<Bc * Tc, 256>>>(p_out);

    // 4. O = (E @ C^T) * inv  -> expected_ctx
    gemm_hmma<Sc, false><<<dim3(Dc / 128, Tc / 128, Bc), 256, SMEM_TOTAL>>>(
        (const __nv_bfloat16*)pEhi, (const __nv_bfloat16*)pElo,
        (const __nv_bfloat16*)pCthi, (const __nv_bfloat16*)pCtlo,
        nullptr, expected_out, nullptr, nullptr,
        Sc, Sc, Dc, (size_t)Tc * Sc, (size_t)Dc * Sc, (size_t)Tc * Dc);
}

// round 15
// speedup vs baseline: 1.7465x; 1.6053x over previous
#include <cuda_runtime.h>
#include <cuda_bf16.h>
#include <math.h>
#include <stdint.h>

// Problem dims (fixed by dataset)
#define Bc 8
#define Sc 4096
#define Tc 512
#define Dc 1024

// ---------------------------------------------------------------------------
// Scratch (device globals; no allocations allowed)
// ---------------------------------------------------------------------------
__device__ __nv_bfloat16 g_Cphi [(size_t)Bc * Sc * Dc];   // gathered C rows, hi
__device__ __nv_bfloat16 g_Cplo [(size_t)Bc * Sc * Dc];   // gathered C rows, lo
__device__ __nv_bfloat16 g_Cthi [(size_t)Bc * Dc * Sc];   // gathered+transposed, hi
__device__ __nv_bfloat16 g_Ctlo [(size_t)Bc * Dc * Sc];   // gathered+transposed, lo
__device__ __nv_bfloat16 g_Qhi  [(size_t)Bc * Tc * Dc];
__device__ __nv_bfloat16 g_Qlo  [(size_t)Bc * Tc * Dc];
__device__ __nv_bfloat16 g_Ehi  [(size_t)Bc * Tc * Sc];   // unnormalized exp, compacted cols
__device__ __nv_bfloat16 g_Elo  [(size_t)Bc * Tc * Sc];
__device__ float         g_psum [(size_t)Bc * Tc * 32];
__device__ float         g_inv  [(size_t)Bc * Tc];
__device__ int           g_idx  [(size_t)Bc * Sc];        // j -> s
__device__ int           g_pos  [(size_t)Bc * Sc];        // s -> j (or -1)
__device__ int           g_np   [Bc];
__device__ float         g_p_scratch[(size_t)Bc * Tc * Sc];

// ---------------------------------------------------------------------------
// PTX helpers
// ---------------------------------------------------------------------------
__device__ __forceinline__ uint32_t smem_u32(const void* p) {
    uint32_t a;
    asm("{ .reg .u64 t; cvta.to.shared.u64 t, %1; cvt.u32.u64 %0, t; }" : "=r"(a) : "l"(p));
    return a;
}
__device__ __forceinline__ void cp_async16(uint32_t dst, const void* src) {
    asm volatile("cp.async.cg.shared.global [%0], [%1], 16;" :: "r"(dst), "l"(src));
}
#define CP_COMMIT() asm volatile("cp.async.commit_group;" ::: "memory")
#define CP_WAIT2()  asm volatile("cp.async.wait_group 2;"  ::: "memory")

__device__ __forceinline__ void ldsm_x4(uint32_t* r, uint32_t addr) {
    asm volatile("ldmatrix.sync.aligned.m8n8.x4.shared.b16 {%0,%1,%2,%3}, [%4];"
                 : "=r"(r[0]), "=r"(r[1]), "=r"(r[2]), "=r"(r[3]) : "r"(addr));
}
__device__ __forceinline__ void mma16816(float* d, const uint32_t* a, uint32_t b0, uint32_t b1) {
    asm volatile(
        "mma.sync.aligned.m16n8k16.row.col.f32.bf16.bf16.f32 "
        "{%0,%1,%2,%3}, {%4,%5,%6,%7}, {%8,%9}, {%0,%1,%2,%3};"
        : "+f"(d[0]), "+f"(d[1]), "+f"(d[2]), "+f"(d[3])
        : "r"(a[0]), "r"(a[1]), "r"(a[2]), "r"(a[3]), "r"(b0), "r"(b1));
}

// smem: [0,2048) row sums | [4096, +3*32KB) stages
#define SM_SUMS    0
#define SM_STAGE0  4096
#define TILE_BYTES_ 8192           // 128 rows x 64B
#define STAGE_BYTES 32768
#define SMEM_TOTAL (SM_STAGE0 + 3 * STAGE_BYTES)   // 102400 -> 2 CTAs/SM

// ---------------------------------------------------------------------------
// mask prefix scan per batch: g_idx, g_pos, g_np
// ---------------------------------------------------------------------------
__global__ __launch_bounds__(1024) void scan_kernel(const int* __restrict__ mask)
{
    const int b    = blockIdx.x;
    const int tid  = threadIdx.x;
    const int lane = tid & 31;
    const int wid  = tid >> 5;
    __shared__ int swarp[32];

    int m[4], e[4];
    const int base = tid * 4;
    int4 mv = *(const int4*)(mask + (size_t)b * Sc + base);
    m[0] = mv.x; m[1] = mv.y; m[2] = mv.z; m[3] = mv.w;
    e[0] = 0; e[1] = m[0]; e[2] = m[0] + m[1]; e[3] = m[0] + m[1] + m[2];
    int tot = e[3] + m[3];

    int inc = tot;
#pragma unroll
    for (int off = 1; off < 32; off <<= 1) {
        int n = __shfl_up_sync(0xffffffffu, inc, off);
        if (lane >= off) inc += n;
    }
    if (lane == 31) swarp[wid] = inc;
    __syncthreads();
    if (wid == 0) {
        int v = swarp[lane];
        int iv = v;
#pragma unroll
        for (int off = 1; off < 32; off <<= 1) {
            int n = __shfl_up_sync(0xffffffffu, iv, off);
            if (lane >= off) iv += n;
        }
        swarp[lane] = iv - v;            // exclusive
        if (lane == 31) g_np[b] = iv;    // total
    }
    __syncthreads();
    const int offset = swarp[wid] + (inc - tot);
#pragma unroll
    for (int i = 0; i < 4; i++) {
        int s = base + i;
        if (m[i]) {
            int j = offset + e[i];
            g_idx[(size_t)b * Sc + j] = s;
            g_pos[(size_t)b * Sc + s] = j;
        } else {
            g_pos[(size_t)b * Sc + s] = -1;
        }
    }
}

// ---------------------------------------------------------------------------
// Gather C rows (idx) -> (Cphi, Cplo) [j][d] and transposed (Cthi, Ctlo) [d][j]
// ---------------------------------------------------------------------------
__global__ __launch_bounds__(256) void gatherC_kernel(const float* __restrict__ C)
{
    __shared__ float tile[32][33];
    const int b  = blockIdx.z;
    const int j0 = blockIdx.y * 32;
    const int d0 = blockIdx.x * 32;
    const int np   = g_np[b];
    const int npad = (np + 127) & ~127;
    if (j0 >= npad) return;
    const int tx = threadIdx.x;   // 0..15
    const int ty = threadIdx.y;   // 0..15

#pragma unroll
    for (int h = 0; h < 2; h++) {
        int r = ty + h * 16;
        int j = j0 + r;
        float2 v = make_float2(0.0f, 0.0f);
        if (j < np) {
            int s = g_idx[(size_t)b * Sc + j];
            v = *(const float2*)(C + ((size_t)b * Sc + s) * Dc + d0 + 2 * tx);
        }
        tile[r][2 * tx]     = v.x;
        tile[r][2 * tx + 1] = v.y;
        size_t gi = ((size_t)b * Sc + j) * Dc + d0 + 2 * tx;
        __nv_bfloat162 hh = __floats2bfloat162_rn(v.x, v.y);
        float lx = v.x - __bfloat162float(__low2bfloat16(hh));
        float ly = v.y - __bfloat162float(__high2bfloat16(hh));
        __nv_bfloat162 ll = __floats2bfloat162_rn(lx, ly);
        *(__nv_bfloat162*)(g_Cphi + gi) = hh;
        *(__nv_bfloat162*)(g_Cplo + gi) = ll;
    }
    __syncthreads();
#pragma unroll
    for (int h = 0; h < 2; h++) {
        int dl = ty + h * 16;
        float a0 = tile[2 * tx][dl];
        float a1 = tile[2 * tx + 1][dl];
        size_t go = ((size_t)b * Dc + d0 + dl) * Sc + j0 + 2 * tx;
        __nv_bfloat162 hh = __floats2bfloat162_rn(a0, a1);
        float lx = a0 - __bfloat162float(__low2bfloat16(hh));
        float ly = a1 - __bfloat162float(__high2bfloat16(hh));
        __nv_bfloat162 ll = __floats2bfloat162_rn(lx, ly);
        *(__nv_bfloat162*)(g_Cthi + go) = hh;
        *(__nv_bfloat162*)(g_Ctlo + go) = ll;
    }
}

// ---------------------------------------------------------------------------
// Convert Q -> (Qhi, Qlo)
// ---------------------------------------------------------------------------
__global__ __launch_bounds__(256) void convert_Q_kernel(const float* __restrict__ Q)
{
    size_t i = ((size_t)blockIdx.x * 256 + threadIdx.x) * 4;
    float4 v = *(const float4*)(Q + i);
    __nv_bfloat162 h01 = __floats2bfloat162_rn(v.x, v.y);
    __nv_bfloat162 h23 = __floats2bfloat162_rn(v.z, v.w);
    __nv_bfloat162 l01 = __floats2bfloat162_rn(v.x - __bfloat162float(__low2bfloat16(h01)),
                                               v.y - __bfloat162float(__high2bfloat16(h01)));
    __nv_bfloat162 l23 = __floats2bfloat162_rn(v.z - __bfloat162float(__low2bfloat16(h23)),
                                               v.w - __bfloat162float(__high2bfloat16(h23)));
    *(__nv_bfloat162*)(g_Qhi + i)     = h01;
    *(__nv_bfloat162*)(g_Qhi + i + 2) = h23;
    *(__nv_bfloat162*)(g_Qlo + i)     = l01;
    *(__nv_bfloat162*)(g_Qlo + i + 2) = l23;
}

// ---------------------------------------------------------------------------
// bf16x3 split GEMM via mma.sync, compacted S dimension.
// CTA tile 128x128, 8 warps (2x4), BK=32, 3-stage cp.async, 2 CTAs/SM.
// IS_QK: n = compacted j, tiles >= npad exit (zero psum); epilogue E=exp, E=0
// for j>=np, row-sum partials. Else (PV): k-loop bound = npad, scale by g_inv.
// ---------------------------------------------------------------------------
template <bool IS_QK>
__global__ __launch_bounds__(256, 2) void gemm_hmma(
    const __nv_bfloat16* __restrict__ Ahi, const __nv_bfloat16* __restrict__ Alo,
    const __nv_bfloat16* __restrict__ Bhi, const __nv_bfloat16* __restrict__ Blo,
    float* __restrict__ Out,
    __nv_bfloat16* __restrict__ EOhi, __nv_bfloat16* __restrict__ EOlo,
    int lda, int ldb, int ldo, size_t strA, size_t strB, size_t strO)
{
    extern __shared__ __align__(1024) char smem[];
    const uint32_t sb  = smem_u32(smem);
    const int tid  = threadIdx.x;
    const int lane = tid & 31;
    const int wid  = tid >> 5;
    const int wm   = wid & 1;
    const int wn   = wid >> 1;
    const int b    = blockIdx.z;
    const int n0   = blockIdx.x * 128;
    const int m0   = blockIdx.y * 128;

    const int np   = g_np[b];
    const int npad = (np + 127) & ~127;
    int nst;
    if (IS_QK) {
        if (n0 >= npad) {    // masked-out tile: contribute zero partials
            if (tid < 128)
                g_psum[((size_t)b * Tc + m0 + tid) * 32 + blockIdx.x] = 0.0f;
            return;
        }
        nst = Dc / 32;
    } else {
        nst = npad >> 5;
    }

    // ---- cp.async load geometry ----
    uint32_t swz[2];
    size_t   ga[2], gb[2];
#pragma unroll
    for (int j = 0; j < 2; j++) {
        int within = tid + 256 * j;
        int row = within >> 2;
        int u   = within & 3;
        swz[j] = (uint32_t)(row * 64 + ((u * 16) ^ (((row >> 1) & 3) << 4)));
        ga[j]  = (size_t)(m0 + row) * lda + u * 8;
        gb[j]  = (size_t)(n0 + row) * ldb + u * 8;
    }
    const __nv_bfloat16* Ah = Ahi + (size_t)b * strA;
    const __nv_bfloat16* Al = Alo + (size_t)b * strA;
    const __nv_bfloat16* Bh = Bhi + (size_t)b * strB;
    const __nv_bfloat16* Bl = Blo + (size_t)b * strB;

    auto load_stage = [&](int k) {
        const uint32_t stg = sb + SM_STAGE0 + (k % 3) * STAGE_BYTES;
        const int kelt = k * 32;
#pragma unroll
        for (int j = 0; j < 2; j++) {
            cp_async16(stg + 0 * TILE_BYTES_ + swz[j], Ah + ga[j] + kelt);
            cp_async16(stg + 1 * TILE_BYTES_ + swz[j], Al + ga[j] + kelt);
            cp_async16(stg + 2 * TILE_BYTES_ + swz[j], Bh + gb[j] + kelt);
            cp_async16(stg + 3 * TILE_BYTES_ + swz[j], Bl + gb[j] + kelt);
        }
    };

    // ---- ldmatrix lane addressing ----
    uint32_t apart[4], aswz[4];
#pragma unroll
    for (int mt = 0; mt < 4; mt++) {
        int r = wm * 64 + mt * 16 + (lane & 15);
        apart[mt] = (uint32_t)r * 64;
        aswz[mt]  = (uint32_t)(((r >> 1) & 3) << 4);
    }
    const uint32_t acol = (uint32_t)((lane >> 4) * 16);
    uint32_t bpart[2], bswz[2];
    {
        int g  = lane >> 3;
        int lr = lane & 7;
        int j  = g >> 1;
#pragma unroll
        for (int p = 0; p < 2; p++) {
            int r = wn * 32 + p * 16 + j * 8 + lr;
            bpart[p] = (uint32_t)r * 64;
            bswz[p]  = (uint32_t)(((r >> 1) & 3) << 4);
        }
    }
    const uint32_t bcol = (uint32_t)((lane >> 3) & 1) * 16;

    float acc[4][4][4];
#pragma unroll
    for (int mt = 0; mt < 4; mt++)
#pragma unroll
        for (int nt = 0; nt < 4; nt++)
#pragma unroll
            for (int f = 0; f < 4; f++) acc[mt][nt][f] = 0.0f;

    // ---- pipeline ----
    load_stage(0); CP_COMMIT();
    load_stage(1); CP_COMMIT();

    for (int k = 0; k < nst; k++) {
        if (k + 2 < nst) load_stage(k + 2);
        CP_COMMIT();
        CP_WAIT2();
        __syncthreads();

        const uint32_t stg = sb + SM_STAGE0 + (k % 3) * STAGE_BYTES;
#pragma unroll
        for (int kk = 0; kk < 32; kk += 16) {
            uint32_t ahi[4][4], alo[4][4], bhi[2][4], blo[2][4];
            const uint32_t ac = (uint32_t)(kk * 2) + acol;
            const uint32_t bc = (uint32_t)(kk * 2) + bcol;
#pragma unroll
            for (int mt = 0; mt < 4; mt++) {
                ldsm_x4(ahi[mt], stg + 0 * TILE_BYTES_ + apart[mt] + (ac ^ aswz[mt]));
                ldsm_x4(alo[mt], stg + 1 * TILE_BYTES_ + apart[mt] + (ac ^ aswz[mt]));
            }
#pragma unroll
            for (int p = 0; p < 2; p++) {
                ldsm_x4(bhi[p], stg + 2 * TILE_BYTES_ + bpart[p] + (bc ^ bswz[p]));
                ldsm_x4(blo[p], stg + 3 * TILE_BYTES_ + bpart[p] + (bc ^ bswz[p]));
            }
#pragma unroll
            for (int mt = 0; mt < 4; mt++)
#pragma unroll
                for (int nt = 0; nt < 4; nt++) {
                    const int p = nt >> 1, o = (nt & 1) * 2;
                    mma16816(acc[mt][nt], ahi[mt], bhi[p][o], bhi[p][o + 1]);
                    mma16816(acc[mt][nt], ahi[mt], blo[p][o], blo[p][o + 1]);
                    mma16816(acc[mt][nt], alo[mt], bhi[p][o], bhi[p][o + 1]);
                }
        }
        __syncthreads();
    }

    // ---- epilogue ----
    const int r0 = lane >> 2;
    const int c0 = (lane & 3) * 2;

    if (IS_QK) {
        const float scale = 0.03125f;  // 1/sqrt(1024)
        __nv_bfloat16* Eh = EOhi + (size_t)b * strO;
        __nv_bfloat16* El = EOlo + (size_t)b * strO;
        float rs[4][2];
#pragma unroll
        for (int mt = 0; mt < 4; mt++) { rs[mt][0] = 0.0f; rs[mt][1] = 0.0f; }

#pragma unroll
        for (int mt = 0; mt < 4; mt++) {
            const int row = m0 + wm * 64 + mt * 16 + r0;
#pragma unroll
            for (int nt = 0; nt < 4; nt++) {
                const int col = n0 + wn * 32 + nt * 8 + c0;   // compacted j
                float* d = acc[mt][nt];
                float e00 = (col     < np) ? __expf(d[0] * scale) : 0.0f;
                float e01 = (col + 1 < np) ? __expf(d[1] * scale) : 0.0f;
                float e10 = (col     < np) ? __expf(d[2] * scale) : 0.0f;
                float e11 = (col + 1 < np) ? __expf(d[3] * scale) : 0.0f;
                rs[mt][0] += e00 + e01;
                rs[mt][1] += e10 + e11;
                __nv_bfloat162 h0 = __floats2bfloat162_rn(e00, e01);
                __nv_bfloat162 h1 = __floats2bfloat162_rn(e10, e11);
                __nv_bfloat162 l0 = __floats2bfloat162_rn(e00 - __bfloat162float(__low2bfloat16(h0)),
                                                          e01 - __bfloat162float(__high2bfloat16(h0)));
                __nv_bfloat162 l1 = __floats2bfloat162_rn(e10 - __bfloat162float(__low2bfloat16(h1)),
                                                          e11 - __bfloat162float(__high2bfloat16(h1)));
                *(__nv_bfloat162*)(Eh + (size_t)row * ldo + col)       = h0;
                *(__nv_bfloat162*)(Eh + (size_t)(row + 8) * ldo + col) = h1;
                *(__nv_bfloat162*)(El + (size_t)row * ldo + col)       = l0;
                *(__nv_bfloat162*)(El + (size_t)(row + 8) * ldo + col) = l1;
            }
        }
        float* ssum = (float*)(smem + SM_SUMS);   // [128 rows][4 warp-cols]
#pragma unroll
        for (int mt = 0; mt < 4; mt++)
#pragma unroll
            for (int half = 0; half < 2; half++) {
                float r = rs[mt][half];
                r += __shfl_xor_sync(0xffffffffu, r, 1);
                r += __shfl_xor_sync(0xffffffffu, r, 2);
                if ((lane & 3) == 0) {
                    int rloc = wm * 64 + mt * 16 + half * 8 + r0;
                    ssum[rloc * 4 + wn] = r;
                }
            }
        __syncthreads();
        if (tid < 128) {
            float t = ssum[tid * 4 + 0] + ssum[tid * 4 + 1]
                    + ssum[tid * 4 + 2] + ssum[tid * 4 + 3];
            g_psum[((size_t)b * Tc + m0 + tid) * 32 + blockIdx.x] = t;
        }
    } else {
        float* Ob = Out + (size_t)b * strO;
        const float* invb = g_inv + (size_t)b * Tc;
#pragma unroll
        for (int mt = 0; mt < 4; mt++) {
            const int row = m0 + wm * 64 + mt * 16 + r0;
            const float i0 = invb[row];
            const float i1 = invb[row + 8];
#pragma unroll
            for (int nt = 0; nt < 4; nt++) {
                const int col = n0 + wn * 32 + nt * 8 + c0;
                float* d = acc[mt][nt];
                *(float2*)(Ob + (size_t)row * ldo + col)       = make_float2(d[0] * i0, d[1] * i0);
                *(float2*)(Ob + (size_t)(row + 8) * ldo + col) = make_float2(d[2] * i1, d[3] * i1);
            }
        }
    }
}

// ---------------------------------------------------------------------------
// inv_kernel: g_inv[row] = 1 / sum(g_psum[row][0..31])
// ---------------------------------------------------------------------------
__global__ __launch_bounds__(256) void inv_kernel()
{
    const int row = blockIdx.x * 256 + threadIdx.x;
    const float* ps = g_psum + (size_t)row * 32;
    float s = 0.0f;
#pragma unroll
    for (int i = 0; i < 32; i++) s += ps[i];
    g_inv[row] = 1.0f / s;
}

// ---------------------------------------------------------------------------
// pctx_kernel: p_ctx[t][s] = pos[s]<0 ? 0 : (Ehi+Elo)[t][pos[s]] * inv[t]
// ---------------------------------------------------------------------------
__global__ __launch_bounds__(256) void pctx_kernel(float* __restrict__ P)
{
    const size_t row = blockIdx.x;          // b*Tc + t
    const int b = (int)(row / Tc);
    const float inv = g_inv[row];
    const int base = threadIdx.x * 16;
    const int* pos = g_pos + (size_t)b * Sc + base;
    const __nv_bfloat16* eh = g_Ehi + row * Sc;
    const __nv_bfloat16* el = g_Elo + row * Sc;
    float* p = P + row * Sc + base;
#pragma unroll
    for (int q = 0; q < 4; q++) {
        int4 j4 = *(const int4*)(pos + q * 4);
        float4 a;
        a.x = (j4.x < 0) ? 0.0f : (__bfloat162float(eh[j4.x]) + __bfloat162float(el[j4.x])) * inv;
        a.y = (j4.y < 0) ? 0.0f : (__bfloat162float(eh[j4.y]) + __bfloat162float(el[j4.y])) * inv;
        a.z = (j4.z < 0) ? 0.0f : (__bfloat162float(eh[j4.z]) + __bfloat162float(el[j4.z])) * inv;
        a.w = (j4.w < 0) ? 0.0f : (__bfloat162float(eh[j4.w]) + __bfloat162float(el[j4.w])) * inv;
        *(float4*)(p + q * 4) = a;
    }
}

// ---------------------------------------------------------------------------
// Launch
// ---------------------------------------------------------------------------
extern "C" void kernel_launch(void* const* d_in, const int* in_sizes, int n_in,
                              void* d_out, int out_size)
{
    const float* ctx   = (const float*)d_in[0];
    const float* query = (const float*)d_in[1];
    const int*   mask  = (const int*)d_in[2];
    float* out = (float*)d_out;

    const size_t BTD = (size_t)Bc * Tc * Dc;
    const size_t BTS = (size_t)Bc * Tc * Sc;

    float* expected_out = out;
    float* p_out;
    if ((size_t)out_size >= BTD + BTS) {
        p_out = out + BTD;
    } else {
        void* sp = nullptr;
        cudaGetSymbolAddress(&sp, g_p_scratch);
        p_out = (float*)sp;
    }

    void *pCphi, *pCplo, *pCthi, *pCtlo, *pQhi, *pQlo, *pEhi, *pElo;
    cudaGetSymbolAddress(&pCphi, g_Cphi);
    cudaGetSymbolAddress(&pCplo, g_Cplo);
    cudaGetSymbolAddress(&pCthi, g_Cthi);
    cudaGetSymbolAddress(&pCtlo, g_Ctlo);
    cudaGetSymbolAddress(&pQhi,  g_Qhi);
    cudaGetSymbolAddress(&pQlo,  g_Qlo);
    cudaGetSymbolAddress(&pEhi,  g_Ehi);
    cudaGetSymbolAddress(&pElo,  g_Elo);

    cudaFuncSetAttribute(gemm_hmma<true>,  cudaFuncAttributeMaxDynamicSharedMemorySize, SMEM_TOTAL);
    cudaFuncSetAttribute(gemm_hmma<false>, cudaFuncAttributeMaxDynamicSharedMemorySize, SMEM_TOTAL);

    // 1. Mask compaction + converts
    scan_kernel<<<Bc, 1024>>>(mask);
    convert_Q_kernel<<<(unsigned)(BTD / 4 / 256), 256>>>(query);
    gatherC_kernel<<<dim3(Dc / 32, Sc / 32, Bc), dim3(16, 16)>>>(ctx);

    // 2. QK^T over compacted columns -> E (bf16 hi/lo) + row-sum partials
    gemm_hmma<true><<<dim3(Sc / 128, Tc / 128, Bc), 256, SMEM_TOTAL>>>(
        (const __nv_bfloat16*)pQhi, (const __nv_bfloat16*)pQlo,
        (const __nv_bfloat16*)pCphi, (const __nv_bfloat16*)pCplo,
        nullptr, (__nv_bfloat16*)pEhi, (__nv_bfloat16*)pElo,
        Dc, Dc, Sc, (size_t)Tc * Dc, (size_t)Sc * Dc, (size_t)Tc * Sc);

    // 3. Row-sum inverses; p_ctx scatter stream
    inv_kernel<<<Bc * Tc / 256, 256>>>();
    pctx_kernel<<<Bc * Tc, 256>>>(p_out);

    // 4. O = (E @ Cpack^T) * inv  (k-loop over compacted range)
    gemm_hmma<false><<<dim3(Dc / 128, Tc / 128, Bc), 256, SMEM_TOTAL>>>(
        (const __nv_bfloat16*)pEhi, (const __nv_bfloat16*)pElo,
        (const __nv_bfloat16*)pCthi, (const __nv_bfloat16*)pCtlo,
        expected_out, nullptr, nullptr,
        Sc, Sc, Dc, (size_t)Tc * Sc, (size_t)Dc * Sc, (size_t)Tc * Dc);
}